// round 1
// baseline (speedup 1.0000x reference)
#include <cuda_runtime.h>
#include <cuda_bf16.h>
#include <math.h>

// ---------------- problem constants ----------------
constexpr int cB = 2, cS = 2048, cV = 32000, cE = 512, cH = 8, cL = 4;
constexpr int cDH = 64, cM = 256, cCHUNK = 128;
constexpr int cBS = cB * cS;                 // 4096 rows
constexpr int cBH = cB * cH;                 // 16
constexpr int cNC = cS / cCHUNK;             // 16 chunks
constexpr int DSPLIT = 4;                    // d-split for attention
constexpr int DC = cDH / DSPLIT;             // 16 d-cols per block

// ---------------- scratch ----------------
constexpr size_t OFF_X    = 0;
constexpr size_t OFF_H    = OFF_X + (size_t)cBS * cE;
constexpr size_t OFF_Q    = OFF_H + (size_t)cBS * cE;
constexpr size_t OFF_K    = OFF_Q + (size_t)cBS * cE;
constexpr size_t OFF_V    = OFF_K + (size_t)cBS * cE;
constexpr size_t OFF_O    = OFF_V + (size_t)cBS * cE;
constexpr size_t OFF_FFN  = OFF_O + (size_t)cBS * cE;
constexpr size_t OFF_QF   = OFF_FFN + (size_t)cBS * 4 * cE;
constexpr size_t OFF_KF   = OFF_QF + (size_t)cBH * cS * cM;
constexpr size_t OFF_KD   = OFF_KF + (size_t)cBH * cS * cM;
constexpr size_t OFF_GMAX = OFF_KD + (size_t)cBH * cS;
constexpr size_t SCRATCH_FLOATS = OFF_GMAX + 64;

__device__ float g_scratch[SCRATCH_FLOATS];

// ---------------- helpers ----------------
__device__ __forceinline__ void atomicMaxFloat(float* addr, float value) {
    if (value >= 0.f) atomicMax((int*)addr, __float_as_int(value));
    else              atomicMin((unsigned int*)addr, __float_as_uint(value));
}

// ---------------- embed + posenc + LN ----------------
__global__ void embed_ln_kernel(const int* __restrict__ src, const float* __restrict__ emb,
                                const float* __restrict__ g, const float* __restrict__ bpar,
                                float* __restrict__ x)
{
    __shared__ float row[cE];
    __shared__ float red[256];
    int r = blockIdx.x;
    int s = r % cS;
    int tid = threadIdx.x;
    int tok = src[r];
    const float kPos = -9.210340371976184f / (float)cE;  // -ln(10000)/E
    for (int e = tid; e < cE; e += 256) {
        int twoj = e & ~1;
        float div = expf((float)twoj * kPos);
        float ang = (float)s * div;
        float pe = (e & 1) ? cosf(ang) : sinf(ang);
        row[e] = emb[(size_t)tok * cE + e] + pe;
    }
    __syncthreads();
    float a0 = row[tid], a1 = row[tid + 256];
    red[tid] = a0 + a1;
    __syncthreads();
    for (int sft = 128; sft > 0; sft >>= 1) { if (tid < sft) red[tid] += red[tid + sft]; __syncthreads(); }
    float mu = red[0] * (1.f / cE);
    __syncthreads();
    float d0 = a0 - mu, d1 = a1 - mu;
    red[tid] = d0 * d0 + d1 * d1;
    __syncthreads();
    for (int sft = 128; sft > 0; sft >>= 1) { if (tid < sft) red[tid] += red[tid + sft]; __syncthreads(); }
    float rstd = rsqrtf(red[0] * (1.f / cE) + 1e-5f);
    x[(size_t)r * cE + tid]       = d0 * rstd * g[tid]       + bpar[tid];
    x[(size_t)r * cE + tid + 256] = d1 * rstd * g[tid + 256] + bpar[tid + 256];
}

// ---------------- generic LN ----------------
__global__ void ln_kernel(const float* __restrict__ in, const float* __restrict__ g,
                          const float* __restrict__ bpar, float* __restrict__ out)
{
    __shared__ float red[256];
    int r = blockIdx.x;
    int tid = threadIdx.x;
    float a0 = in[(size_t)r * cE + tid];
    float a1 = in[(size_t)r * cE + tid + 256];
    red[tid] = a0 + a1;
    __syncthreads();
    for (int sft = 128; sft > 0; sft >>= 1) { if (tid < sft) red[tid] += red[tid + sft]; __syncthreads(); }
    float mu = red[0] * (1.f / cE);
    __syncthreads();
    float d0 = a0 - mu, d1 = a1 - mu;
    red[tid] = d0 * d0 + d1 * d1;
    __syncthreads();
    for (int sft = 128; sft > 0; sft >>= 1) { if (tid < sft) red[tid] += red[tid + sft]; __syncthreads(); }
    float rstd = rsqrtf(red[0] * (1.f / cE) + 1e-5f);
    out[(size_t)r * cE + tid]       = d0 * rstd * g[tid]       + bpar[tid];
    out[(size_t)r * cE + tid + 256] = d1 * rstd * g[tid + 256] + bpar[tid + 256];
}

// ---------------- SGEMM 128x128x8, 8x8 microtile ----------------
// C[M,N] = epilogue(A[M,K] @ B[K,N]); act=1 -> exact GELU after bias; res added after act.
__global__ void sgemm128(const float* __restrict__ A, const float* __restrict__ Bm,
                         const float* __restrict__ bias, const float* __restrict__ res,
                         float* __restrict__ C, int Mrows, int N, int K, int act)
{
    __shared__ float As[8][128];
    __shared__ float Bs[8][128];
    int tid = threadIdx.x;
    int row0 = blockIdx.y * 128, col0 = blockIdx.x * 128;
    int tx = tid & 15, ty = tid >> 4;
    int a_row = tid >> 1;
    int a_col = (tid & 1) * 4;
    int b_row = tid >> 5;
    int b_col = (tid & 31) * 4;
    const float* Aptr = A + (size_t)(row0 + a_row) * K + a_col;
    const float* Bptr = Bm + (size_t)b_row * N + col0 + b_col;

    float acc[8][8];
#pragma unroll
    for (int i = 0; i < 8; i++)
#pragma unroll
        for (int j = 0; j < 8; j++) acc[i][j] = 0.f;

    for (int kt = 0; kt < K; kt += 8) {
        float4 av = *(const float4*)(Aptr + kt);
        float4 bv = *(const float4*)(Bptr + (size_t)kt * N);
        As[a_col + 0][a_row] = av.x;
        As[a_col + 1][a_row] = av.y;
        As[a_col + 2][a_row] = av.z;
        As[a_col + 3][a_row] = av.w;
        *(float4*)&Bs[b_row][b_col] = bv;
        __syncthreads();
#pragma unroll
        for (int kk = 0; kk < 8; kk++) {
            float4 a0 = *(const float4*)&As[kk][ty * 8];
            float4 a1 = *(const float4*)&As[kk][ty * 8 + 4];
            float4 b0 = *(const float4*)&Bs[kk][tx * 8];
            float4 b1 = *(const float4*)&Bs[kk][tx * 8 + 4];
            float fa[8] = {a0.x, a0.y, a0.z, a0.w, a1.x, a1.y, a1.z, a1.w};
            float fb[8] = {b0.x, b0.y, b0.z, b0.w, b1.x, b1.y, b1.z, b1.w};
#pragma unroll
            for (int i = 0; i < 8; i++)
#pragma unroll
                for (int j = 0; j < 8; j++) acc[i][j] += fa[i] * fb[j];
        }
        __syncthreads();
    }
#pragma unroll
    for (int i = 0; i < 8; i++) {
        int row = row0 + ty * 8 + i;
#pragma unroll
        for (int j = 0; j < 8; j++) {
            int col = col0 + tx * 8 + j;
            float v = acc[i][j];
            if (bias) v += bias[col];
            if (act)  v = 0.5f * v * (1.f + erff(v * 0.70710678118654752f));
            if (res)  v += res[(size_t)row * N + col];
            C[(size_t)row * N + col] = v;
        }
    }
}

// ---------------- FAVOR+ features ----------------
// q/k stored [B*S, E]; features out [BH, S, M]
__global__ void feat_q_kernel(const float* __restrict__ q, const float* __restrict__ proj,
                              float* __restrict__ qf)
{
    __shared__ float xr[cDH];
    __shared__ float red[256];
    int sIdx = blockIdx.x;
    int bh = blockIdx.y;
    int b = bh / cH, h = bh % cH;
    int m = threadIdx.x;
    size_t r = (size_t)b * cS + sIdx;
    if (m < cDH) xr[m] = q[r * cE + h * cDH + m];
    __syncthreads();
    const float* pr = proj + (size_t)m * cDH;
    float dot = 0.f, ssq = 0.f;
#pragma unroll
    for (int d = 0; d < cDH; d++) { dot += xr[d] * pr[d]; ssq += xr[d] * xr[d]; }
    const float dn = 0.35355339059327373f;   // 64^-0.25
    float xd = dot * dn;
    float diag = 0.5f * ssq * dn * dn;
    red[m] = xd;
    __syncthreads();
    for (int sft = 128; sft > 0; sft >>= 1) { if (m < sft) red[m] = fmaxf(red[m], red[m + sft]); __syncthreads(); }
    float mx = red[0];
    qf[((size_t)bh * cS + sIdx) * cM + m] = 0.0625f * (expf(xd - diag - mx) + 1e-4f);
}

__global__ void init_gmax_kernel(float* gmax) { *gmax = -3.4e38f; }

__global__ void feat_k1_kernel(const float* __restrict__ k, const float* __restrict__ proj,
                               float* __restrict__ kf, float* __restrict__ kdiag,
                               float* __restrict__ gmax)
{
    __shared__ float xr[cDH];
    __shared__ float red[256];
    int sIdx = blockIdx.x;
    int bh = blockIdx.y;
    int b = bh / cH, h = bh % cH;
    int m = threadIdx.x;
    size_t r = (size_t)b * cS + sIdx;
    if (m < cDH) xr[m] = k[r * cE + h * cDH + m];
    __syncthreads();
    const float* pr = proj + (size_t)m * cDH;
    float dot = 0.f, ssq = 0.f;
#pragma unroll
    for (int d = 0; d < cDH; d++) { dot += xr[d] * pr[d]; ssq += xr[d] * xr[d]; }
    const float dn = 0.35355339059327373f;
    float xd = dot * dn;
    kf[((size_t)bh * cS + sIdx) * cM + m] = xd;
    if (m == 0) kdiag[(size_t)bh * cS + sIdx] = 0.5f * ssq * dn * dn;
    red[m] = xd;
    __syncthreads();
    for (int sft = 128; sft > 0; sft >>= 1) { if (m < sft) red[m] = fmaxf(red[m], red[m + sft]); __syncthreads(); }
    if (m == 0) atomicMaxFloat(gmax, red[0]);
}

__global__ void feat_k2_kernel(float* __restrict__ kf, const float* __restrict__ kdiag,
                               const float* __restrict__ gmax)
{
    float gm = *gmax;
    size_t total = (size_t)cBH * cS * cM;
    for (size_t i = (size_t)blockIdx.x * blockDim.x + threadIdx.x; i < total;
         i += (size_t)gridDim.x * blockDim.x) {
        kf[i] = 0.0625f * (expf(kf[i] - kdiag[i >> 8] - gm) + 1e-4f);
    }
}

// ---------------- chunked causal linear attention ----------------
// grid (DSPLIT, BH), 256 threads, dynamic smem
constexpr int SDC = DC + 1;  // padded Ssum stride = 17
constexpr int ASTR = cCHUNK + 1;  // 129
constexpr size_t ATT_SMEM_FLOATS =
    (size_t)cM * SDC       // Ssum  4352
    + cM                   // zsum   256
    + cCHUNK * ASTR        // Ash  16512
    + cCHUNK * DC          // vsh   2048
    + 64 * ASTR            // qsh   8256
    + 64 * ASTR            // ksh   8256
    + cCHUNK;              // densh  128
constexpr size_t ATT_SMEM_BYTES = ATT_SMEM_FLOATS * 4;

__global__ void attention_kernel(const float* __restrict__ qf, const float* __restrict__ kf,
                                 const float* __restrict__ v, float* __restrict__ o)
{
    extern __shared__ float sm[];
    float* Ssum  = sm;
    float* zsum  = Ssum + (size_t)cM * SDC;
    float* Ash   = zsum + cM;
    float* vsh   = Ash + (size_t)cCHUNK * ASTR;
    float* qsh   = vsh + (size_t)cCHUNK * DC;
    float* ksh   = qsh + (size_t)64 * ASTR;
    float* densh = ksh + (size_t)64 * ASTR;

    int ds = blockIdx.x;
    int bh = blockIdx.y;
    int b = bh / cH, h = bh % cH;
    int tid = threadIdx.x;
    int tx = tid & 15, ty = tid >> 4;
    int cc = tid & 127, dp = tid >> 7;   // dp in {0,1}

    const float* qf_b = qf + (size_t)bh * cS * cM;
    const float* kf_b = kf + (size_t)bh * cS * cM;
    const float* v_b  = v + (size_t)b * cS * cE + h * cDH + ds * DC;
    float*       o_b  = o + (size_t)b * cS * cE + h * cDH + ds * DC;

    for (int i = tid; i < cM * SDC; i += 256) Ssum[i] = 0.f;
    if (tid < cM) zsum[tid] = 0.f;
    __syncthreads();

    for (int ch = 0; ch < cNC; ch++) {
        int c0 = ch * cCHUNK;
        // load v chunk slice
        for (int i = tid; i < cCHUNK * DC; i += 256) {
            int c = i / DC, d = i % DC;
            vsh[i] = v_b[(size_t)(c0 + c) * cE + d];
        }
        float accA[8][8];
#pragma unroll
        for (int i = 0; i < 8; i++)
#pragma unroll
            for (int j = 0; j < 8; j++) accA[i][j] = 0.f;
        float num1[8] = {0, 0, 0, 0, 0, 0, 0, 0};
        float den1 = 0.f;
        __syncthreads();

        for (int mt = 0; mt < cM / 64; mt++) {
            // stage q/k m-tiles, transposed [mm][c]
            for (int i = tid; i < 64 * cCHUNK; i += 256) {
                int mm = i & 63;
                int c = i >> 6;
                size_t gidx = (size_t)(c0 + c) * cM + mt * 64 + mm;
                qsh[mm * ASTR + c] = qf_b[gidx];
                ksh[mm * ASTR + c] = kf_b[gidx];
            }
            __syncthreads();
            // A partial: thread owns 8x8 of [128x128]
            for (int mm = 0; mm < 64; mm++) {
                float fq[8], fk[8];
#pragma unroll
                for (int i = 0; i < 8; i++) fq[i] = qsh[mm * ASTR + ty * 8 + i];
#pragma unroll
                for (int j = 0; j < 8; j++) fk[j] = ksh[mm * ASTR + tx * 8 + j];
#pragma unroll
                for (int i = 0; i < 8; i++)
#pragma unroll
                    for (int j = 0; j < 8; j++) accA[i][j] += fq[i] * fk[j];
            }
            // num1/den1 partial: thread owns (c=cc, 8 d-values at dp*8)
            for (int mm = 0; mm < 64; mm++) {
                float qv = qsh[mm * ASTR + cc];
                int m = mt * 64 + mm;
#pragma unroll
                for (int j = 0; j < 8; j++) num1[j] += qv * Ssum[m * SDC + dp * 8 + j];
                if (dp == 0) den1 += qv * zsum[m];
            }
            __syncthreads();
        }
        // write masked A
#pragma unroll
        for (int i = 0; i < 8; i++) {
            int c = ty * 8 + i;
#pragma unroll
            for (int j = 0; j < 8; j++) {
                int t = tx * 8 + j;
                Ash[c * ASTR + t] = (t <= c) ? accA[i][j] : 0.f;
            }
        }
        __syncthreads();
        // num2/den2 from A @ v
        float num2[8] = {0, 0, 0, 0, 0, 0, 0, 0};
        float den2 = 0.f;
        for (int t = 0; t < cCHUNK; t++) {
            float a = Ash[cc * ASTR + t];
#pragma unroll
            for (int j = 0; j < 8; j++) num2[j] += a * vsh[t * DC + dp * 8 + j];
            if (dp == 0) den2 += a;
        }
        if (dp == 0) densh[cc] = den1 + den2;
        __syncthreads();
        float den = densh[cc] + 1e-6f;
#pragma unroll
        for (int j = 0; j < 8; j++)
            o_b[(size_t)(c0 + cc) * cE + dp * 8 + j] = (num1[j] + num2[j]) / den;

        // state update: thread m = tid handles Ssum row m (+ zsum)
        {
            int m = tid;
            float sreg[DC];
#pragma unroll
            for (int d = 0; d < DC; d++) sreg[d] = 0.f;
            float zacc = 0.f;
            for (int c = 0; c < cCHUNK; c++) {
                float kv = kf_b[(size_t)(c0 + c) * cM + m];
                zacc += kv;
                const float* vr = &vsh[c * DC];
#pragma unroll
                for (int d = 0; d < DC; d++) sreg[d] += kv * vr[d];
            }
#pragma unroll
            for (int d = 0; d < DC; d++) Ssum[m * SDC + d] += sreg[d];
            zsum[m] += zacc;
        }
        __syncthreads();
    }
}

// ---------------- host orchestration ----------------
extern "C" void kernel_launch(void* const* d_in, const int* in_sizes, int n_in,
                              void* d_out, int out_size)
{
    const int*   src  = (const int*)d_in[0];
    const float* emb  = (const float*)d_in[2];
    const float* lng  = (const float*)d_in[3];
    const float* lnb  = (const float*)d_in[4];
    const float* Wq   = (const float*)d_in[5];
    const float* Wk   = (const float*)d_in[6];
    const float* Wv   = (const float*)d_in[7];
    const float* Wo   = (const float*)d_in[8];
    const float* ln1g = (const float*)d_in[9];
    const float* ln1b = (const float*)d_in[10];
    const float* W1   = (const float*)d_in[11];
    const float* b1   = (const float*)d_in[12];
    const float* W2   = (const float*)d_in[13];
    const float* b2   = (const float*)d_in[14];
    const float* ln2g = (const float*)d_in[15];
    const float* ln2b = (const float*)d_in[16];
    const float* proj = (const float*)d_in[17];
    const float* fcw  = (const float*)d_in[18];
    const float* fcb  = (const float*)d_in[19];
    float* out = (float*)d_out;

    float* sc = nullptr;
    cudaGetSymbolAddress((void**)&sc, g_scratch);
    float* x    = sc + OFF_X;
    float* h    = sc + OFF_H;
    float* q    = sc + OFF_Q;
    float* k    = sc + OFF_K;
    float* v    = sc + OFF_V;
    float* o    = sc + OFF_O;
    float* ffn  = sc + OFF_FFN;
    float* qf   = sc + OFF_QF;
    float* kf   = sc + OFF_KF;
    float* kd   = sc + OFF_KD;
    float* gmax = sc + OFF_GMAX;

    cudaFuncSetAttribute(attention_kernel, cudaFuncAttributeMaxDynamicSharedMemorySize,
                         (int)ATT_SMEM_BYTES);

    embed_ln_kernel<<<cBS, 256>>>(src, emb, lng, lnb, x);

    dim3 g512(cE / 128, cBS / 128);
    dim3 gF1(4 * cE / 128, cBS / 128);
    dim3 gFeat(cS, cBH);
    dim3 gAtt(DSPLIT, cBH);

    for (int l = 0; l < cL; l++) {
        ln_kernel<<<cBS, 256>>>(x, ln1g + (size_t)l * cE, ln1b + (size_t)l * cE, h);
        sgemm128<<<g512, 256>>>(h, Wq + (size_t)l * cE * cE, nullptr, nullptr, q, cBS, cE, cE, 0);
        sgemm128<<<g512, 256>>>(h, Wk + (size_t)l * cE * cE, nullptr, nullptr, k, cBS, cE, cE, 0);
        sgemm128<<<g512, 256>>>(h, Wv + (size_t)l * cE * cE, nullptr, nullptr, v, cBS, cE, cE, 0);

        const float* pl = proj + (size_t)l * cM * cDH;
        feat_q_kernel<<<gFeat, 256>>>(q, pl, qf);
        init_gmax_kernel<<<1, 1>>>(gmax);
        feat_k1_kernel<<<gFeat, 256>>>(k, pl, kf, kd, gmax);
        feat_k2_kernel<<<4096, 256>>>(kf, kd, gmax);

        attention_kernel<<<gAtt, 256, ATT_SMEM_BYTES>>>(qf, kf, v, o);

        sgemm128<<<g512, 256>>>(o, Wo + (size_t)l * cE * cE, nullptr, x, x, cBS, cE, cE, 0);

        ln_kernel<<<cBS, 256>>>(x, ln2g + (size_t)l * cE, ln2b + (size_t)l * cE, h);
        sgemm128<<<gF1, 256>>>(h, W1 + (size_t)l * cE * 4 * cE, b1 + (size_t)l * 4 * cE,
                               nullptr, ffn, cBS, 4 * cE, cE, 1);
        sgemm128<<<g512, 256>>>(ffn, W2 + (size_t)l * 4 * cE * cE, b2 + (size_t)l * cE,
                                x, x, cBS, cE, 4 * cE, 0);
    }

    sgemm128<<<dim3(cV / 128, cBS / 128), 256>>>(x, fcw, fcb, nullptr, out, cBS, cV, cE, 0);
}

// round 2
// speedup vs baseline: 1.2186x; 1.2186x over previous
#include <cuda_runtime.h>
#include <cuda_bf16.h>
#include <math.h>

// ---------------- problem constants ----------------
constexpr int cB = 2, cS = 2048, cV = 32000, cE = 512, cH = 8, cL = 4;
constexpr int cDH = 64, cM = 256, cCHUNK = 128;
constexpr int cBS = cB * cS;                 // 4096 rows
constexpr int cBH = cB * cH;                 // 16
constexpr int cNC = cS / cCHUNK;             // 16 chunks
constexpr int DSPLIT = 4;                    // d-split for attention
constexpr int DC = cDH / DSPLIT;             // 16 d-cols per block

// ---------------- scratch ----------------
constexpr size_t OFF_X    = 0;
constexpr size_t OFF_H    = OFF_X + (size_t)cBS * cE;
constexpr size_t OFF_Q    = OFF_H + (size_t)cBS * cE;
constexpr size_t OFF_K    = OFF_Q + (size_t)cBS * cE;
constexpr size_t OFF_V    = OFF_K + (size_t)cBS * cE;
constexpr size_t OFF_O    = OFF_V + (size_t)cBS * cE;
constexpr size_t OFF_FFN  = OFF_O + (size_t)cBS * cE;
constexpr size_t OFF_QF   = OFF_FFN + (size_t)cBS * 4 * cE;
constexpr size_t OFF_KF   = OFF_QF + (size_t)cBH * cS * cM;
constexpr size_t OFF_KD   = OFF_KF + (size_t)cBH * cS * cM;
constexpr size_t OFF_GMAX = OFF_KD + (size_t)cBH * cS;
constexpr size_t SCRATCH_FLOATS = OFF_GMAX + 64;

__device__ float g_scratch[SCRATCH_FLOATS];

// ---------------- helpers ----------------
__device__ __forceinline__ void atomicMaxFloat(float* addr, float value) {
    if (value >= 0.f) atomicMax((int*)addr, __float_as_int(value));
    else              atomicMin((unsigned int*)addr, __float_as_uint(value));
}

__device__ __forceinline__ unsigned f2tf32(float x) {
    unsigned r;
    asm("cvt.rna.tf32.f32 %0, %1;" : "=r"(r) : "f"(x));
    return r;
}

__device__ __forceinline__ void mma_tf32(float* c, const unsigned* a, unsigned b0, unsigned b1) {
    asm volatile("mma.sync.aligned.m16n8k8.row.col.f32.tf32.tf32.f32 "
        "{%0,%1,%2,%3}, {%4,%5,%6,%7}, {%8,%9}, {%0,%1,%2,%3};"
        : "+f"(c[0]), "+f"(c[1]), "+f"(c[2]), "+f"(c[3])
        : "r"(a[0]), "r"(a[1]), "r"(a[2]), "r"(a[3]), "r"(b0), "r"(b1));
}

// ---------------- embed + posenc + LN ----------------
__global__ void embed_ln_kernel(const int* __restrict__ src, const float* __restrict__ emb,
                                const float* __restrict__ g, const float* __restrict__ bpar,
                                float* __restrict__ x)
{
    __shared__ float row[cE];
    __shared__ float red[256];
    int r = blockIdx.x;
    int s = r % cS;
    int tid = threadIdx.x;
    int tok = src[r];
    const float kPos = -9.210340371976184f / (float)cE;  // -ln(10000)/E
    for (int e = tid; e < cE; e += 256) {
        int twoj = e & ~1;
        float div = expf((float)twoj * kPos);
        float ang = (float)s * div;
        float pe = (e & 1) ? cosf(ang) : sinf(ang);
        row[e] = emb[(size_t)tok * cE + e] + pe;
    }
    __syncthreads();
    float a0 = row[tid], a1 = row[tid + 256];
    red[tid] = a0 + a1;
    __syncthreads();
    for (int sft = 128; sft > 0; sft >>= 1) { if (tid < sft) red[tid] += red[tid + sft]; __syncthreads(); }
    float mu = red[0] * (1.f / cE);
    __syncthreads();
    float d0 = a0 - mu, d1 = a1 - mu;
    red[tid] = d0 * d0 + d1 * d1;
    __syncthreads();
    for (int sft = 128; sft > 0; sft >>= 1) { if (tid < sft) red[tid] += red[tid + sft]; __syncthreads(); }
    float rstd = rsqrtf(red[0] * (1.f / cE) + 1e-5f);
    x[(size_t)r * cE + tid]       = d0 * rstd * g[tid]       + bpar[tid];
    x[(size_t)r * cE + tid + 256] = d1 * rstd * g[tid + 256] + bpar[tid + 256];
}

// ---------------- generic LN ----------------
__global__ void ln_kernel(const float* __restrict__ in, const float* __restrict__ g,
                          const float* __restrict__ bpar, float* __restrict__ out)
{
    __shared__ float red[256];
    int r = blockIdx.x;
    int tid = threadIdx.x;
    float a0 = in[(size_t)r * cE + tid];
    float a1 = in[(size_t)r * cE + tid + 256];
    red[tid] = a0 + a1;
    __syncthreads();
    for (int sft = 128; sft > 0; sft >>= 1) { if (tid < sft) red[tid] += red[tid + sft]; __syncthreads(); }
    float mu = red[0] * (1.f / cE);
    __syncthreads();
    float d0 = a0 - mu, d1 = a1 - mu;
    red[tid] = d0 * d0 + d1 * d1;
    __syncthreads();
    for (int sft = 128; sft > 0; sft >>= 1) { if (tid < sft) red[tid] += red[tid + sft]; __syncthreads(); }
    float rstd = rsqrtf(red[0] * (1.f / cE) + 1e-5f);
    out[(size_t)r * cE + tid]       = d0 * rstd * g[tid]       + bpar[tid];
    out[(size_t)r * cE + tid + 256] = d1 * rstd * g[tid + 256] + bpar[tid + 256];
}

// ---------------- TF32 tensor-core GEMM ----------------
// C[M,N] = epilogue(A[M,K] @ B[K,N]); 128x128 CTA tile, BK=16, 8 warps of 64x32.
// act=1 -> exact GELU after bias; res added after act.
__global__ __launch_bounds__(256, 2)
void gemm_tf32(const float* __restrict__ A, const float* __restrict__ Bm,
               const float* __restrict__ bias, const float* __restrict__ res,
               float* __restrict__ C, int N, int K, int act)
{
    __shared__ unsigned As[16][136];   // [k][m], stride 136 -> bank = 8*t4+g (conflict-free frag loads)
    __shared__ unsigned Bs[16][136];   // [k][n]

    int tid = threadIdx.x;
    int warp = tid >> 5, lane = tid & 31;
    int wm = warp >> 2, wn = warp & 3;          // warp tile origin (wm*64, wn*32)
    int g = lane >> 2, t4 = lane & 3;
    int row0 = blockIdx.y * 128, col0 = blockIdx.x * 128;

    // global load mapping
    int ar = tid >> 1;                 // A row within tile (0..127)
    int ac = (tid & 1) * 8;            // A col offset within 16-wide k tile
    int br = tid >> 4;                 // B k-row (0..15)
    int bc = (tid & 15) * 8;           // B col offset (0..120)

    const float* Ap = A + (size_t)(row0 + ar) * K + ac;
    const float* Bp = Bm + (size_t)br * N + col0 + bc;

    float acc[4][4][4];
#pragma unroll
    for (int mi = 0; mi < 4; mi++)
#pragma unroll
        for (int ni = 0; ni < 4; ni++)
#pragma unroll
            for (int q = 0; q < 4; q++) acc[mi][ni][q] = 0.f;

    // prefetch tile 0
    float4 av0 = *(const float4*)(Ap);
    float4 av1 = *(const float4*)(Ap + 4);
    float4 bv0 = *(const float4*)(Bp);
    float4 bv1 = *(const float4*)(Bp + 4);

    for (int kt = 0; kt < K; kt += 16) {
        // store staged tile (converted to tf32 bit patterns)
        As[ac + 0][ar] = f2tf32(av0.x);
        As[ac + 1][ar] = f2tf32(av0.y);
        As[ac + 2][ar] = f2tf32(av0.z);
        As[ac + 3][ar] = f2tf32(av0.w);
        As[ac + 4][ar] = f2tf32(av1.x);
        As[ac + 5][ar] = f2tf32(av1.y);
        As[ac + 6][ar] = f2tf32(av1.z);
        As[ac + 7][ar] = f2tf32(av1.w);
        uint4 bw0 = {f2tf32(bv0.x), f2tf32(bv0.y), f2tf32(bv0.z), f2tf32(bv0.w)};
        uint4 bw1 = {f2tf32(bv1.x), f2tf32(bv1.y), f2tf32(bv1.z), f2tf32(bv1.w)};
        *(uint4*)&Bs[br][bc]     = bw0;
        *(uint4*)&Bs[br][bc + 4] = bw1;
        __syncthreads();

        // prefetch next tile
        if (kt + 16 < K) {
            av0 = *(const float4*)(Ap + kt + 16);
            av1 = *(const float4*)(Ap + kt + 20);
            bv0 = *(const float4*)(Bp + (size_t)(kt + 16) * N);
            bv1 = *(const float4*)(Bp + (size_t)(kt + 16) * N + 4);
        }

        // compute: two k-steps of 8
#pragma unroll
        for (int ks = 0; ks < 16; ks += 8) {
            unsigned af[4][4];
#pragma unroll
            for (int mi = 0; mi < 4; mi++) {
                int m = wm * 64 + mi * 16 + g;
                af[mi][0] = As[ks + t4][m];
                af[mi][1] = As[ks + t4][m + 8];
                af[mi][2] = As[ks + t4 + 4][m];
                af[mi][3] = As[ks + t4 + 4][m + 8];
            }
#pragma unroll
            for (int ni = 0; ni < 4; ni++) {
                int n = wn * 32 + ni * 8 + g;
                unsigned bf0 = Bs[ks + t4][n];
                unsigned bf1 = Bs[ks + t4 + 4][n];
#pragma unroll
                for (int mi = 0; mi < 4; mi++)
                    mma_tf32(acc[mi][ni], af[mi], bf0, bf1);
            }
        }
        __syncthreads();
    }

    // epilogue
#pragma unroll
    for (int mi = 0; mi < 4; mi++) {
#pragma unroll
        for (int ni = 0; ni < 4; ni++) {
            int row = row0 + wm * 64 + mi * 16 + g;
            int col = col0 + wn * 32 + ni * 8 + 2 * t4;
#pragma unroll
            for (int half = 0; half < 2; half++) {
                int r = row + half * 8;
                float v0 = acc[mi][ni][half * 2 + 0];
                float v1 = acc[mi][ni][half * 2 + 1];
                if (bias) { v0 += bias[col]; v1 += bias[col + 1]; }
                if (act) {
                    v0 = 0.5f * v0 * (1.f + erff(v0 * 0.70710678118654752f));
                    v1 = 0.5f * v1 * (1.f + erff(v1 * 0.70710678118654752f));
                }
                if (res) {
                    v0 += res[(size_t)r * N + col];
                    v1 += res[(size_t)r * N + col + 1];
                }
                *(float2*)&C[(size_t)r * N + col] = make_float2(v0, v1);
            }
        }
    }
}

// ---------------- FAVOR+ features ----------------
__global__ void feat_q_kernel(const float* __restrict__ q, const float* __restrict__ proj,
                              float* __restrict__ qf)
{
    __shared__ float xr[cDH];
    __shared__ float red[256];
    int sIdx = blockIdx.x;
    int bh = blockIdx.y;
    int b = bh / cH, h = bh % cH;
    int m = threadIdx.x;
    size_t r = (size_t)b * cS + sIdx;
    if (m < cDH) xr[m] = q[r * cE + h * cDH + m];
    __syncthreads();
    const float* pr = proj + (size_t)m * cDH;
    float dot = 0.f, ssq = 0.f;
#pragma unroll
    for (int d = 0; d < cDH; d++) { dot += xr[d] * pr[d]; ssq += xr[d] * xr[d]; }
    const float dn = 0.35355339059327373f;   // 64^-0.25
    float xd = dot * dn;
    float diag = 0.5f * ssq * dn * dn;
    red[m] = xd;
    __syncthreads();
    for (int sft = 128; sft > 0; sft >>= 1) { if (m < sft) red[m] = fmaxf(red[m], red[m + sft]); __syncthreads(); }
    float mx = red[0];
    qf[((size_t)bh * cS + sIdx) * cM + m] = 0.0625f * (expf(xd - diag - mx) + 1e-4f);
}

__global__ void init_gmax_kernel(float* gmax) { *gmax = -3.4e38f; }

__global__ void feat_k1_kernel(const float* __restrict__ k, const float* __restrict__ proj,
                               float* __restrict__ kf, float* __restrict__ kdiag,
                               float* __restrict__ gmax)
{
    __shared__ float xr[cDH];
    __shared__ float red[256];
    int sIdx = blockIdx.x;
    int bh = blockIdx.y;
    int b = bh / cH, h = bh % cH;
    int m = threadIdx.x;
    size_t r = (size_t)b * cS + sIdx;
    if (m < cDH) xr[m] = k[r * cE + h * cDH + m];
    __syncthreads();
    const float* pr = proj + (size_t)m * cDH;
    float dot = 0.f, ssq = 0.f;
#pragma unroll
    for (int d = 0; d < cDH; d++) { dot += xr[d] * pr[d]; ssq += xr[d] * xr[d]; }
    const float dn = 0.35355339059327373f;
    float xd = dot * dn;
    kf[((size_t)bh * cS + sIdx) * cM + m] = xd;
    if (m == 0) kdiag[(size_t)bh * cS + sIdx] = 0.5f * ssq * dn * dn;
    red[m] = xd;
    __syncthreads();
    for (int sft = 128; sft > 0; sft >>= 1) { if (m < sft) red[m] = fmaxf(red[m], red[m + sft]); __syncthreads(); }
    if (m == 0) atomicMaxFloat(gmax, red[0]);
}

__global__ void feat_k2_kernel(float* __restrict__ kf, const float* __restrict__ kdiag,
                               const float* __restrict__ gmax)
{
    float gm = *gmax;
    size_t total = (size_t)cBH * cS * cM;
    for (size_t i = (size_t)blockIdx.x * blockDim.x + threadIdx.x; i < total;
         i += (size_t)gridDim.x * blockDim.x) {
        kf[i] = 0.0625f * (expf(kf[i] - kdiag[i >> 8] - gm) + 1e-4f);
    }
}

// ---------------- chunked causal linear attention ----------------
constexpr int SDC = DC + 1;       // 17
constexpr int ASTR = cCHUNK + 1;  // 129
constexpr size_t ATT_SMEM_FLOATS =
    (size_t)cM * SDC + cM + cCHUNK * ASTR + cCHUNK * DC + 64 * ASTR + 64 * ASTR + cCHUNK;
constexpr size_t ATT_SMEM_BYTES = ATT_SMEM_FLOATS * 4;

__global__ void attention_kernel(const float* __restrict__ qf, const float* __restrict__ kf,
                                 const float* __restrict__ v, float* __restrict__ o)
{
    extern __shared__ float sm[];
    float* Ssum  = sm;
    float* zsum  = Ssum + (size_t)cM * SDC;
    float* Ash   = zsum + cM;
    float* vsh   = Ash + (size_t)cCHUNK * ASTR;
    float* qsh   = vsh + (size_t)cCHUNK * DC;
    float* ksh   = qsh + (size_t)64 * ASTR;
    float* densh = ksh + (size_t)64 * ASTR;

    int ds = blockIdx.x;
    int bh = blockIdx.y;
    int b = bh / cH, h = bh % cH;
    int tid = threadIdx.x;
    int tx = tid & 15, ty = tid >> 4;
    int cc = tid & 127, dp = tid >> 7;

    const float* qf_b = qf + (size_t)bh * cS * cM;
    const float* kf_b = kf + (size_t)bh * cS * cM;
    const float* v_b  = v + (size_t)b * cS * cE + h * cDH + ds * DC;
    float*       o_b  = o + (size_t)b * cS * cE + h * cDH + ds * DC;

    for (int i = tid; i < cM * SDC; i += 256) Ssum[i] = 0.f;
    if (tid < cM) zsum[tid] = 0.f;
    __syncthreads();

    for (int ch = 0; ch < cNC; ch++) {
        int c0 = ch * cCHUNK;
        for (int i = tid; i < cCHUNK * DC; i += 256) {
            int c = i / DC, d = i % DC;
            vsh[i] = v_b[(size_t)(c0 + c) * cE + d];
        }
        float accA[8][8];
#pragma unroll
        for (int i = 0; i < 8; i++)
#pragma unroll
            for (int j = 0; j < 8; j++) accA[i][j] = 0.f;
        float num1[8] = {0, 0, 0, 0, 0, 0, 0, 0};
        float den1 = 0.f;
        __syncthreads();

        for (int mt = 0; mt < cM / 64; mt++) {
            for (int i = tid; i < 64 * cCHUNK; i += 256) {
                int mm = i & 63;
                int c = i >> 6;
                size_t gidx = (size_t)(c0 + c) * cM + mt * 64 + mm;
                qsh[mm * ASTR + c] = qf_b[gidx];
                ksh[mm * ASTR + c] = kf_b[gidx];
            }
            __syncthreads();
            for (int mm = 0; mm < 64; mm++) {
                float fq[8], fk[8];
#pragma unroll
                for (int i = 0; i < 8; i++) fq[i] = qsh[mm * ASTR + ty * 8 + i];
#pragma unroll
                for (int j = 0; j < 8; j++) fk[j] = ksh[mm * ASTR + tx * 8 + j];
#pragma unroll
                for (int i = 0; i < 8; i++)
#pragma unroll
                    for (int j = 0; j < 8; j++) accA[i][j] += fq[i] * fk[j];
            }
            for (int mm = 0; mm < 64; mm++) {
                float qv = qsh[mm * ASTR + cc];
                int m = mt * 64 + mm;
#pragma unroll
                for (int j = 0; j < 8; j++) num1[j] += qv * Ssum[m * SDC + dp * 8 + j];
                if (dp == 0) den1 += qv * zsum[m];
            }
            __syncthreads();
        }
#pragma unroll
        for (int i = 0; i < 8; i++) {
            int c = ty * 8 + i;
#pragma unroll
            for (int j = 0; j < 8; j++) {
                int t = tx * 8 + j;
                Ash[c * ASTR + t] = (t <= c) ? accA[i][j] : 0.f;
            }
        }
        __syncthreads();
        float num2[8] = {0, 0, 0, 0, 0, 0, 0, 0};
        float den2 = 0.f;
        for (int t = 0; t < cCHUNK; t++) {
            float a = Ash[cc * ASTR + t];
#pragma unroll
            for (int j = 0; j < 8; j++) num2[j] += a * vsh[t * DC + dp * 8 + j];
            if (dp == 0) den2 += a;
        }
        if (dp == 0) densh[cc] = den1 + den2;
        __syncthreads();
        float den = densh[cc] + 1e-6f;
#pragma unroll
        for (int j = 0; j < 8; j++)
            o_b[(size_t)(c0 + cc) * cE + dp * 8 + j] = (num1[j] + num2[j]) / den;

        {
            int m = tid;
            float sreg[DC];
#pragma unroll
            for (int d = 0; d < DC; d++) sreg[d] = 0.f;
            float zacc = 0.f;
            for (int c = 0; c < cCHUNK; c++) {
                float kv = kf_b[(size_t)(c0 + c) * cM + m];
                zacc += kv;
                const float* vr = &vsh[c * DC];
#pragma unroll
                for (int d = 0; d < DC; d++) sreg[d] += kv * vr[d];
            }
#pragma unroll
            for (int d = 0; d < DC; d++) Ssum[m * SDC + d] += sreg[d];
            zsum[m] += zacc;
        }
        __syncthreads();
    }
}

// ---------------- host orchestration ----------------
extern "C" void kernel_launch(void* const* d_in, const int* in_sizes, int n_in,
                              void* d_out, int out_size)
{
    const int*   src  = (const int*)d_in[0];
    const float* emb  = (const float*)d_in[2];
    const float* lng  = (const float*)d_in[3];
    const float* lnb  = (const float*)d_in[4];
    const float* Wq   = (const float*)d_in[5];
    const float* Wk   = (const float*)d_in[6];
    const float* Wv   = (const float*)d_in[7];
    const float* Wo   = (const float*)d_in[8];
    const float* ln1g = (const float*)d_in[9];
    const float* ln1b = (const float*)d_in[10];
    const float* W1   = (const float*)d_in[11];
    const float* b1   = (const float*)d_in[12];
    const float* W2   = (const float*)d_in[13];
    const float* b2   = (const float*)d_in[14];
    const float* ln2g = (const float*)d_in[15];
    const float* ln2b = (const float*)d_in[16];
    const float* proj = (const float*)d_in[17];
    const float* fcw  = (const float*)d_in[18];
    const float* fcb  = (const float*)d_in[19];
    float* out = (float*)d_out;

    float* sc = nullptr;
    cudaGetSymbolAddress((void**)&sc, g_scratch);
    float* x    = sc + OFF_X;
    float* h    = sc + OFF_H;
    float* q    = sc + OFF_Q;
    float* k    = sc + OFF_K;
    float* v    = sc + OFF_V;
    float* o    = sc + OFF_O;
    float* ffn  = sc + OFF_FFN;
    float* qf   = sc + OFF_QF;
    float* kf   = sc + OFF_KF;
    float* kd   = sc + OFF_KD;
    float* gmax = sc + OFF_GMAX;

    cudaFuncSetAttribute(attention_kernel, cudaFuncAttributeMaxDynamicSharedMemorySize,
                         (int)ATT_SMEM_BYTES);

    embed_ln_kernel<<<cBS, 256>>>(src, emb, lng, lnb, x);

    dim3 g512(cE / 128, cBS / 128);
    dim3 gF1(4 * cE / 128, cBS / 128);
    dim3 gFeat(cS, cBH);
    dim3 gAtt(DSPLIT, cBH);

    for (int l = 0; l < cL; l++) {
        ln_kernel<<<cBS, 256>>>(x, ln1g + (size_t)l * cE, ln1b + (size_t)l * cE, h);
        gemm_tf32<<<g512, 256>>>(h, Wq + (size_t)l * cE * cE, nullptr, nullptr, q, cE, cE, 0);
        gemm_tf32<<<g512, 256>>>(h, Wk + (size_t)l * cE * cE, nullptr, nullptr, k, cE, cE, 0);
        gemm_tf32<<<g512, 256>>>(h, Wv + (size_t)l * cE * cE, nullptr, nullptr, v, cE, cE, 0);

        const float* pl = proj + (size_t)l * cM * cDH;
        feat_q_kernel<<<gFeat, 256>>>(q, pl, qf);
        init_gmax_kernel<<<1, 1>>>(gmax);
        feat_k1_kernel<<<gFeat, 256>>>(k, pl, kf, kd, gmax);
        feat_k2_kernel<<<4096, 256>>>(kf, kd, gmax);

        attention_kernel<<<gAtt, 256, ATT_SMEM_BYTES>>>(qf, kf, v, o);

        gemm_tf32<<<g512, 256>>>(o, Wo + (size_t)l * cE * cE, nullptr, x, x, cE, cE, 0);

        ln_kernel<<<cBS, 256>>>(x, ln2g + (size_t)l * cE, ln2b + (size_t)l * cE, h);
        gemm_tf32<<<gF1, 256>>>(h, W1 + (size_t)l * cE * 4 * cE, b1 + (size_t)l * 4 * cE,
                                nullptr, ffn, 4 * cE, cE, 1);
        gemm_tf32<<<g512, 256>>>(ffn, W2 + (size_t)l * 4 * cE * cE, b2 + (size_t)l * cE,
                                 x, x, cE, 4 * cE, 0);
    }

    gemm_tf32<<<dim3(cV / 128, cBS / 128), 256>>>(x, fcw, fcb, nullptr, out, cV, cE, 0);
}

// round 3
// speedup vs baseline: 5.6425x; 4.6303x over previous
#include <cuda_runtime.h>
#include <cuda_bf16.h>
#include <math.h>

// ---------------- problem constants ----------------
constexpr int cB = 2, cS = 2048, cV = 32000, cE = 512, cH = 8, cL = 4;
constexpr int cDH = 64, cM = 256, cCHUNK = 128;
constexpr int cBS = cB * cS;                 // 4096 rows
constexpr int cBH = cB * cH;                 // 16
constexpr int cNC = cS / cCHUNK;             // 16 chunks

// ---------------- scratch ----------------
constexpr size_t OFF_X    = 0;
constexpr size_t OFF_H    = OFF_X + (size_t)cBS * cE;
constexpr size_t OFF_Q    = OFF_H + (size_t)cBS * cE;
constexpr size_t OFF_K    = OFF_Q + (size_t)cBS * cE;
constexpr size_t OFF_V    = OFF_K + (size_t)cBS * cE;
constexpr size_t OFF_O    = OFF_V + (size_t)cBS * cE;
constexpr size_t OFF_FFN  = OFF_O + (size_t)cBS * cE;
constexpr size_t OFF_QF   = OFF_FFN + (size_t)cBS * 4 * cE;
constexpr size_t OFF_KF   = OFF_QF + (size_t)cBH * cS * cM;
constexpr size_t OFF_KD   = OFF_KF + (size_t)cBH * cS * cM;
constexpr size_t OFF_KV   = OFF_KD + (size_t)cBH * cS;          // kvsum [bh][nc][256][64]
constexpr size_t OFF_ZC   = OFF_KV + (size_t)cBH * cNC * cM * cDH;
constexpr size_t OFF_GMAX = OFF_ZC + (size_t)cBH * cNC * cM;
constexpr size_t SCRATCH_FLOATS = OFF_GMAX + 64;

__device__ float g_scratch[SCRATCH_FLOATS];

// ---------------- helpers ----------------
__device__ __forceinline__ void atomicMaxFloat(float* addr, float value) {
    if (value >= 0.f) atomicMax((int*)addr, __float_as_int(value));
    else              atomicMin((unsigned int*)addr, __float_as_uint(value));
}

__device__ __forceinline__ unsigned f2tf32(float x) {
    unsigned r;
    asm("cvt.rna.tf32.f32 %0, %1;" : "=r"(r) : "f"(x));
    return r;
}

__device__ __forceinline__ void mma_tf32(float* c, const unsigned* a, unsigned b0, unsigned b1) {
    asm volatile("mma.sync.aligned.m16n8k8.row.col.f32.tf32.tf32.f32 "
        "{%0,%1,%2,%3}, {%4,%5,%6,%7}, {%8,%9}, {%0,%1,%2,%3};"
        : "+f"(c[0]), "+f"(c[1]), "+f"(c[2]), "+f"(c[3])
        : "r"(a[0]), "r"(a[1]), "r"(a[2]), "r"(a[3]), "r"(b0), "r"(b1));
}

// ---------------- embed + posenc + LN ----------------
__global__ void embed_ln_kernel(const int* __restrict__ src, const float* __restrict__ emb,
                                const float* __restrict__ g, const float* __restrict__ bpar,
                                float* __restrict__ x)
{
    __shared__ float row[cE];
    __shared__ float red[256];
    int r = blockIdx.x;
    int s = r % cS;
    int tid = threadIdx.x;
    int tok = src[r];
    const float kPos = -9.210340371976184f / (float)cE;
    for (int e = tid; e < cE; e += 256) {
        int twoj = e & ~1;
        float div = expf((float)twoj * kPos);
        float ang = (float)s * div;
        float pe = (e & 1) ? cosf(ang) : sinf(ang);
        row[e] = emb[(size_t)tok * cE + e] + pe;
    }
    __syncthreads();
    float a0 = row[tid], a1 = row[tid + 256];
    red[tid] = a0 + a1;
    __syncthreads();
    for (int sft = 128; sft > 0; sft >>= 1) { if (tid < sft) red[tid] += red[tid + sft]; __syncthreads(); }
    float mu = red[0] * (1.f / cE);
    __syncthreads();
    float d0 = a0 - mu, d1 = a1 - mu;
    red[tid] = d0 * d0 + d1 * d1;
    __syncthreads();
    for (int sft = 128; sft > 0; sft >>= 1) { if (tid < sft) red[tid] += red[tid + sft]; __syncthreads(); }
    float rstd = rsqrtf(red[0] * (1.f / cE) + 1e-5f);
    x[(size_t)r * cE + tid]       = d0 * rstd * g[tid]       + bpar[tid];
    x[(size_t)r * cE + tid + 256] = d1 * rstd * g[tid + 256] + bpar[tid + 256];
}

__global__ void ln_kernel(const float* __restrict__ in, const float* __restrict__ g,
                          const float* __restrict__ bpar, float* __restrict__ out)
{
    __shared__ float red[256];
    int r = blockIdx.x;
    int tid = threadIdx.x;
    float a0 = in[(size_t)r * cE + tid];
    float a1 = in[(size_t)r * cE + tid + 256];
    red[tid] = a0 + a1;
    __syncthreads();
    for (int sft = 128; sft > 0; sft >>= 1) { if (tid < sft) red[tid] += red[tid + sft]; __syncthreads(); }
    float mu = red[0] * (1.f / cE);
    __syncthreads();
    float d0 = a0 - mu, d1 = a1 - mu;
    red[tid] = d0 * d0 + d1 * d1;
    __syncthreads();
    for (int sft = 128; sft > 0; sft >>= 1) { if (tid < sft) red[tid] += red[tid + sft]; __syncthreads(); }
    float rstd = rsqrtf(red[0] * (1.f / cE) + 1e-5f);
    out[(size_t)r * cE + tid]       = d0 * rstd * g[tid]       + bpar[tid];
    out[(size_t)r * cE + tid + 256] = d1 * rstd * g[tid + 256] + bpar[tid + 256];
}

// ---------------- TF32 tensor-core GEMM ----------------
__global__ __launch_bounds__(256, 2)
void gemm_tf32(const float* __restrict__ A, const float* __restrict__ Bm,
               const float* __restrict__ bias, const float* __restrict__ res,
               float* __restrict__ C, int N, int K, int act)
{
    __shared__ unsigned As[16][136];
    __shared__ unsigned Bs[16][136];

    int tid = threadIdx.x;
    int warp = tid >> 5, lane = tid & 31;
    int wm = warp >> 2, wn = warp & 3;
    int g = lane >> 2, t4 = lane & 3;
    int row0 = blockIdx.y * 128, col0 = blockIdx.x * 128;

    int ar = tid >> 1;
    int ac = (tid & 1) * 8;
    int br = tid >> 4;
    int bc = (tid & 15) * 8;

    const float* Ap = A + (size_t)(row0 + ar) * K + ac;
    const float* Bp = Bm + (size_t)br * N + col0 + bc;

    float acc[4][4][4];
#pragma unroll
    for (int mi = 0; mi < 4; mi++)
#pragma unroll
        for (int ni = 0; ni < 4; ni++)
#pragma unroll
            for (int q = 0; q < 4; q++) acc[mi][ni][q] = 0.f;

    float4 av0 = *(const float4*)(Ap);
    float4 av1 = *(const float4*)(Ap + 4);
    float4 bv0 = *(const float4*)(Bp);
    float4 bv1 = *(const float4*)(Bp + 4);

    for (int kt = 0; kt < K; kt += 16) {
        As[ac + 0][ar] = f2tf32(av0.x);
        As[ac + 1][ar] = f2tf32(av0.y);
        As[ac + 2][ar] = f2tf32(av0.z);
        As[ac + 3][ar] = f2tf32(av0.w);
        As[ac + 4][ar] = f2tf32(av1.x);
        As[ac + 5][ar] = f2tf32(av1.y);
        As[ac + 6][ar] = f2tf32(av1.z);
        As[ac + 7][ar] = f2tf32(av1.w);
        uint4 bw0 = {f2tf32(bv0.x), f2tf32(bv0.y), f2tf32(bv0.z), f2tf32(bv0.w)};
        uint4 bw1 = {f2tf32(bv1.x), f2tf32(bv1.y), f2tf32(bv1.z), f2tf32(bv1.w)};
        *(uint4*)&Bs[br][bc]     = bw0;
        *(uint4*)&Bs[br][bc + 4] = bw1;
        __syncthreads();

        if (kt + 16 < K) {
            av0 = *(const float4*)(Ap + kt + 16);
            av1 = *(const float4*)(Ap + kt + 20);
            bv0 = *(const float4*)(Bp + (size_t)(kt + 16) * N);
            bv1 = *(const float4*)(Bp + (size_t)(kt + 16) * N + 4);
        }

#pragma unroll
        for (int ks = 0; ks < 16; ks += 8) {
            unsigned af[4][4];
#pragma unroll
            for (int mi = 0; mi < 4; mi++) {
                int m = wm * 64 + mi * 16 + g;
                af[mi][0] = As[ks + t4][m];
                af[mi][1] = As[ks + t4][m + 8];
                af[mi][2] = As[ks + t4 + 4][m];
                af[mi][3] = As[ks + t4 + 4][m + 8];
            }
#pragma unroll
            for (int ni = 0; ni < 4; ni++) {
                int n = wn * 32 + ni * 8 + g;
                unsigned bf0 = Bs[ks + t4][n];
                unsigned bf1 = Bs[ks + t4 + 4][n];
#pragma unroll
                for (int mi = 0; mi < 4; mi++)
                    mma_tf32(acc[mi][ni], af[mi], bf0, bf1);
            }
        }
        __syncthreads();
    }

#pragma unroll
    for (int mi = 0; mi < 4; mi++) {
#pragma unroll
        for (int ni = 0; ni < 4; ni++) {
            int row = row0 + wm * 64 + mi * 16 + g;
            int col = col0 + wn * 32 + ni * 8 + 2 * t4;
#pragma unroll
            for (int half = 0; half < 2; half++) {
                int r = row + half * 8;
                float v0 = acc[mi][ni][half * 2 + 0];
                float v1 = acc[mi][ni][half * 2 + 1];
                if (bias) { v0 += bias[col]; v1 += bias[col + 1]; }
                if (act) {
                    v0 = 0.5f * v0 * (1.f + erff(v0 * 0.70710678118654752f));
                    v1 = 0.5f * v1 * (1.f + erff(v1 * 0.70710678118654752f));
                }
                if (res) {
                    v0 += res[(size_t)r * N + col];
                    v1 += res[(size_t)r * N + col + 1];
                }
                *(float2*)&C[(size_t)r * N + col] = make_float2(v0, v1);
            }
        }
    }
}

// fused QKV: grid.x in [0,12): sel = bx/4 chooses Wq/Wk/Wv and output buffer
__global__ __launch_bounds__(256, 2)
void gemm_qkv(const float* __restrict__ A, const float* __restrict__ Bq,
              const float* __restrict__ Bk, const float* __restrict__ Bv,
              float* __restrict__ Cq, float* __restrict__ Ck, float* __restrict__ Cv)
{
    constexpr int N = cE, K = cE;
    __shared__ unsigned As[16][136];
    __shared__ unsigned Bs[16][136];

    int tid = threadIdx.x;
    int warp = tid >> 5, lane = tid & 31;
    int wm = warp >> 2, wn = warp & 3;
    int g = lane >> 2, t4 = lane & 3;
    int bx = blockIdx.x;
    int sel = bx >> 2;
    const float* Bm = sel == 0 ? Bq : (sel == 1 ? Bk : Bv);
    float* C = sel == 0 ? Cq : (sel == 1 ? Ck : Cv);
    int row0 = blockIdx.y * 128, col0 = (bx & 3) * 128;

    int ar = tid >> 1;
    int ac = (tid & 1) * 8;
    int br = tid >> 4;
    int bc = (tid & 15) * 8;

    const float* Ap = A + (size_t)(row0 + ar) * K + ac;
    const float* Bp = Bm + (size_t)br * N + col0 + bc;

    float acc[4][4][4];
#pragma unroll
    for (int mi = 0; mi < 4; mi++)
#pragma unroll
        for (int ni = 0; ni < 4; ni++)
#pragma unroll
            for (int q = 0; q < 4; q++) acc[mi][ni][q] = 0.f;

    float4 av0 = *(const float4*)(Ap);
    float4 av1 = *(const float4*)(Ap + 4);
    float4 bv0 = *(const float4*)(Bp);
    float4 bv1 = *(const float4*)(Bp + 4);

    for (int kt = 0; kt < K; kt += 16) {
        As[ac + 0][ar] = f2tf32(av0.x);
        As[ac + 1][ar] = f2tf32(av0.y);
        As[ac + 2][ar] = f2tf32(av0.z);
        As[ac + 3][ar] = f2tf32(av0.w);
        As[ac + 4][ar] = f2tf32(av1.x);
        As[ac + 5][ar] = f2tf32(av1.y);
        As[ac + 6][ar] = f2tf32(av1.z);
        As[ac + 7][ar] = f2tf32(av1.w);
        uint4 bw0 = {f2tf32(bv0.x), f2tf32(bv0.y), f2tf32(bv0.z), f2tf32(bv0.w)};
        uint4 bw1 = {f2tf32(bv1.x), f2tf32(bv1.y), f2tf32(bv1.z), f2tf32(bv1.w)};
        *(uint4*)&Bs[br][bc]     = bw0;
        *(uint4*)&Bs[br][bc + 4] = bw1;
        __syncthreads();

        if (kt + 16 < K) {
            av0 = *(const float4*)(Ap + kt + 16);
            av1 = *(const float4*)(Ap + kt + 20);
            bv0 = *(const float4*)(Bp + (size_t)(kt + 16) * N);
            bv1 = *(const float4*)(Bp + (size_t)(kt + 16) * N + 4);
        }

#pragma unroll
        for (int ks = 0; ks < 16; ks += 8) {
            unsigned af[4][4];
#pragma unroll
            for (int mi = 0; mi < 4; mi++) {
                int m = wm * 64 + mi * 16 + g;
                af[mi][0] = As[ks + t4][m];
                af[mi][1] = As[ks + t4][m + 8];
                af[mi][2] = As[ks + t4 + 4][m];
                af[mi][3] = As[ks + t4 + 4][m + 8];
            }
#pragma unroll
            for (int ni = 0; ni < 4; ni++) {
                int n = wn * 32 + ni * 8 + g;
                unsigned bf0 = Bs[ks + t4][n];
                unsigned bf1 = Bs[ks + t4 + 4][n];
#pragma unroll
                for (int mi = 0; mi < 4; mi++)
                    mma_tf32(acc[mi][ni], af[mi], bf0, bf1);
            }
        }
        __syncthreads();
    }

#pragma unroll
    for (int mi = 0; mi < 4; mi++) {
#pragma unroll
        for (int ni = 0; ni < 4; ni++) {
            int row = row0 + wm * 64 + mi * 16 + g;
            int col = col0 + wn * 32 + ni * 8 + 2 * t4;
#pragma unroll
            for (int half = 0; half < 2; half++) {
                int r = row + half * 8;
                *(float2*)&C[(size_t)r * N + col] =
                    make_float2(acc[mi][ni][half * 2 + 0], acc[mi][ni][half * 2 + 1]);
            }
        }
    }
}

// ---------------- FAVOR+ features (tiled: 16 seq positions per block) ----------------
constexpr int PST = 65;                    // proj smem stride
constexpr int XDST = 257;                  // xd smem stride
constexpr size_t FEAT_SMEM_FLOATS = (size_t)cM * PST + 16 * 64 + 16 * XDST + 16 + 16;
constexpr size_t FEAT_SMEM_BYTES = FEAT_SMEM_FLOATS * 4;

__global__ void feat_q_kernel(const float* __restrict__ q, const float* __restrict__ proj,
                              float* __restrict__ qf)
{
    extern __shared__ float fsm[];
    float* psh  = fsm;                        // [256][65]
    float* xsh  = psh + (size_t)cM * PST;     // [16][64]
    float* xdsh = xsh + 16 * 64;              // [16][257]
    float* ssq  = xdsh + 16 * XDST;           // [16]
    float* mxsh = ssq + 16;                   // [16]

    int s0 = blockIdx.x * 16;
    int bh = blockIdx.y;
    int b = bh / cH, h = bh % cH;
    int tid = threadIdx.x;
    int m = tid;

    for (int i = tid; i < cM * cDH; i += 256) {
        int mm = i >> 6, d = i & 63;
        psh[mm * PST + d] = proj[i];
    }
    for (int i = tid; i < 16 * 64; i += 256) {
        int s = i >> 6, d = i & 63;
        xsh[i] = q[(size_t)(b * cS + s0 + s) * cE + h * cDH + d];
    }
    __syncthreads();
    if (tid < 16) {
        float acc = 0.f;
#pragma unroll
        for (int d = 0; d < 64; d++) { float xv = xsh[tid * 64 + d]; acc += xv * xv; }
        ssq[tid] = acc;
    }
    const float dn = 0.35355339059327373f;
#pragma unroll
    for (int s = 0; s < 16; s++) {
        float dot = 0.f;
#pragma unroll
        for (int d = 0; d < 64; d++) dot += xsh[s * 64 + d] * psh[m * PST + d];
        xdsh[s * XDST + m] = dot * dn;
    }
    __syncthreads();
    int warp = tid >> 5, lane = tid & 31;
    for (int s = warp; s < 16; s += 8) {
        float mx = -3.4e38f;
#pragma unroll
        for (int i = 0; i < 8; i++) mx = fmaxf(mx, xdsh[s * XDST + lane + i * 32]);
#pragma unroll
        for (int sft = 16; sft > 0; sft >>= 1) mx = fmaxf(mx, __shfl_xor_sync(0xffffffff, mx, sft));
        if (lane == 0) mxsh[s] = mx;
    }
    __syncthreads();
#pragma unroll
    for (int s = 0; s < 16; s++) {
        float diag = 0.5f * ssq[s] * dn * dn;
        qf[((size_t)bh * cS + s0 + s) * cM + m] =
            0.0625f * (expf(xdsh[s * XDST + m] - diag - mxsh[s]) + 1e-4f);
    }
}

__global__ void init_gmax_kernel(float* gmax) { *gmax = -3.4e38f; }

__global__ void feat_k1_kernel(const float* __restrict__ k, const float* __restrict__ proj,
                               float* __restrict__ kf, float* __restrict__ kdiag,
                               float* __restrict__ gmax)
{
    extern __shared__ float fsm[];
    float* psh  = fsm;
    float* xsh  = psh + (size_t)cM * PST;
    float* xdsh = xsh + 16 * 64;
    float* ssq  = xdsh + 16 * XDST;
    float* mxsh = ssq + 16;

    int s0 = blockIdx.x * 16;
    int bh = blockIdx.y;
    int b = bh / cH, h = bh % cH;
    int tid = threadIdx.x;
    int m = tid;

    for (int i = tid; i < cM * cDH; i += 256) {
        int mm = i >> 6, d = i & 63;
        psh[mm * PST + d] = proj[i];
    }
    for (int i = tid; i < 16 * 64; i += 256) {
        int s = i >> 6, d = i & 63;
        xsh[i] = k[(size_t)(b * cS + s0 + s) * cE + h * cDH + d];
    }
    __syncthreads();
    if (tid < 16) {
        float acc = 0.f;
#pragma unroll
        for (int d = 0; d < 64; d++) { float xv = xsh[tid * 64 + d]; acc += xv * xv; }
        ssq[tid] = acc;
    }
    const float dn = 0.35355339059327373f;
    float tmax = -3.4e38f;
#pragma unroll
    for (int s = 0; s < 16; s++) {
        float dot = 0.f;
#pragma unroll
        for (int d = 0; d < 64; d++) dot += xsh[s * 64 + d] * psh[m * PST + d];
        float xd = dot * dn;
        kf[((size_t)bh * cS + s0 + s) * cM + m] = xd;
        tmax = fmaxf(tmax, xd);
    }
    __syncthreads();
    if (tid < 16) kdiag[(size_t)bh * cS + s0 + tid] = 0.5f * ssq[tid] * dn * dn;
    // block max -> global atomic
    int lane = tid & 31;
#pragma unroll
    for (int sft = 16; sft > 0; sft >>= 1) tmax = fmaxf(tmax, __shfl_xor_sync(0xffffffff, tmax, sft));
    if (lane == 0) mxsh[tid >> 5] = tmax;
    __syncthreads();
    if (tid == 0) {
        float mx = mxsh[0];
#pragma unroll
        for (int w = 1; w < 8; w++) mx = fmaxf(mx, mxsh[w]);
        atomicMaxFloat(gmax, mx);
    }
}

__global__ void feat_k2_kernel(float* __restrict__ kf, const float* __restrict__ kdiag,
                               const float* __restrict__ gmax)
{
    float gm = *gmax;
    size_t total = (size_t)cBH * cS * cM;
    for (size_t i = (size_t)blockIdx.x * blockDim.x + threadIdx.x; i < total;
         i += (size_t)gridDim.x * blockDim.x) {
        kf[i] = 0.0625f * (expf(kf[i] - kdiag[i >> 8] - gm) + 1e-4f);
    }
}

// ---------------- attention phase A: per-chunk state sums ----------------
// kvsum[bh][c][m][d] = sum_{i in chunk c} kf[i,m] * v[i,d]; zc[bh][c][m] = sum kf[i,m]
__global__ void attn_chunk_sums(const float* __restrict__ kf, const float* __restrict__ v,
                                float* __restrict__ kvsum, float* __restrict__ zc)
{
    __shared__ float vsh[cCHUNK * cDH];  // 32KB
    int ch = blockIdx.x, bh = blockIdx.y;
    int b = bh / cH, h = bh % cH;
    int tid = threadIdx.x;
    int c0 = ch * cCHUNK;
    const float* v_b = v + (size_t)b * cS * cE + h * cDH;
    for (int i = tid; i < cCHUNK * cDH; i += 256) {
        int c = i >> 6, d = i & 63;
        vsh[i] = v_b[(size_t)(c0 + c) * cE + d];
    }
    __syncthreads();
    int m = tid;
    float acc[cDH];
#pragma unroll
    for (int d = 0; d < cDH; d++) acc[d] = 0.f;
    float zacc = 0.f;
    const float* kf_b = kf + ((size_t)bh * cS + c0) * cM + m;
    for (int i = 0; i < cCHUNK; i++) {
        float kv = kf_b[(size_t)i * cM];
        zacc += kv;
        const float* vr = &vsh[i * cDH];
#pragma unroll
        for (int d = 0; d < cDH; d++) acc[d] += kv * vr[d];
    }
    float* outp = kvsum + (((size_t)bh * cNC + ch) * cM + m) * cDH;
#pragma unroll
    for (int d = 0; d < cDH; d += 4)
        *(float4*)&outp[d] = make_float4(acc[d], acc[d + 1], acc[d + 2], acc[d + 3]);
    zc[((size_t)bh * cNC + ch) * cM + m] = zacc;
}

// ---------------- attention phase B: exclusive prefix over chunks ----------------
__global__ void attn_prefix(float* __restrict__ kvsum, float* __restrict__ zc)
{
    int bh = blockIdx.x, ds = blockIdx.y;   // ds in [0,4): 16 d each
    int m = threadIdx.x;
    int d0 = ds * 16;
    float carry[16];
#pragma unroll
    for (int j = 0; j < 16; j++) carry[j] = 0.f;
    float zcarry = 0.f;
    for (int c = 0; c < cNC; c++) {
        float* p = kvsum + (((size_t)bh * cNC + c) * cM + m) * cDH + d0;
#pragma unroll
        for (int j = 0; j < 16; j += 4) {
            float4 t = *(float4*)&p[j];
            *(float4*)&p[j] = make_float4(carry[j], carry[j + 1], carry[j + 2], carry[j + 3]);
            carry[j] += t.x; carry[j + 1] += t.y; carry[j + 2] += t.z; carry[j + 3] += t.w;
        }
        if (ds == 0) {
            float* zp = zc + ((size_t)bh * cNC + c) * cM + m;
            float t = *zp;
            *zp = zcarry;
            zcarry += t;
        }
    }
}

// ---------------- attention phase C: per-chunk output ----------------
constexpr int ASTR = cCHUNK + 1;  // 129
constexpr size_t ATT_SMEM_FLOATS =
    (size_t)cCHUNK * cDH          // vsh 8192
    + cCHUNK                      // densh 128
    + (size_t)cCHUNK * ASTR       // union: {qsh[64][129], ksh[64][129]} / Ash[128][129] = 16512
    + 64 * 64                     // ssh (S_prev tile) 4096
    + 64;                         // zsh
constexpr size_t ATT_SMEM_BYTES = ATT_SMEM_FLOATS * 4;

__global__ void attn_out(const float* __restrict__ qf, const float* __restrict__ kf,
                         const float* __restrict__ v, const float* __restrict__ kvsum,
                         const float* __restrict__ zc, float* __restrict__ o)
{
    extern __shared__ float sm[];
    float* vsh   = sm;                              // [128][64]
    float* densh = vsh + (size_t)cCHUNK * cDH;      // [128]
    float* uni   = densh + cCHUNK;                  // union region
    float* qsh   = uni;                             // [64][129]
    float* ksh   = uni + (size_t)64 * ASTR;         // [64][129]
    float* Ash   = uni;                             // [128][129] (after mt loop)
    float* ssh   = uni + (size_t)cCHUNK * ASTR;     // [64][64]
    float* zsh   = ssh + 64 * 64;                   // [64]

    int ch = blockIdx.x, bh = blockIdx.y;
    int b = bh / cH, h = bh % cH;
    int tid = threadIdx.x;
    int tx = tid & 15, ty = tid >> 4;
    int cc = tid & 127, dp = tid >> 7;              // dp in {0,1}: 32 d each
    int c0 = ch * cCHUNK;

    const float* qf_b = qf + (size_t)bh * cS * cM;
    const float* kf_b = kf + (size_t)bh * cS * cM;
    const float* v_b  = v + (size_t)b * cS * cE + h * cDH;
    const float* Sp   = kvsum + ((size_t)bh * cNC + ch) * cM * cDH;
    const float* zp   = zc + ((size_t)bh * cNC + ch) * cM;
    float*       o_b  = o + (size_t)b * cS * cE + h * cDH;

    for (int i = tid; i < cCHUNK * cDH; i += 256) {
        int c = i >> 6, d = i & 63;
        vsh[i] = v_b[(size_t)(c0 + c) * cE + d];
    }

    float accA[8][8];
#pragma unroll
    for (int i = 0; i < 8; i++)
#pragma unroll
        for (int j = 0; j < 8; j++) accA[i][j] = 0.f;
    float num1[32];
#pragma unroll
    for (int j = 0; j < 32; j++) num1[j] = 0.f;
    float den1 = 0.f;
    __syncthreads();

    for (int mt = 0; mt < cM / 64; mt++) {
        // stage q/k m-tiles transposed [mm][c], S_prev tile, z tile
        for (int i = tid; i < 64 * cCHUNK; i += 256) {
            int mm = i & 63;
            int c = i >> 6;
            size_t gidx = (size_t)(c0 + c) * cM + mt * 64 + mm;
            qsh[mm * ASTR + c] = qf_b[gidx];
            ksh[mm * ASTR + c] = kf_b[gidx];
        }
        for (int i = tid; i < 64 * 64; i += 256) ssh[i] = Sp[(size_t)(mt * 64) * cDH + i];
        if (tid < 64) zsh[tid] = zp[mt * 64 + tid];
        __syncthreads();
        // A partial: thread owns 8x8 of [128x128]
        for (int mm = 0; mm < 64; mm++) {
            float fq[8], fk[8];
#pragma unroll
            for (int i = 0; i < 8; i++) fq[i] = qsh[mm * ASTR + ty * 8 + i];
#pragma unroll
            for (int j = 0; j < 8; j++) fk[j] = ksh[mm * ASTR + tx * 8 + j];
#pragma unroll
            for (int i = 0; i < 8; i++)
#pragma unroll
                for (int j = 0; j < 8; j++) accA[i][j] += fq[i] * fk[j];
        }
        // num1/den1 partial: thread (cc, dp) covers 32 d
        for (int mm = 0; mm < 64; mm++) {
            float qv = qsh[mm * ASTR + cc];
            const float* sr = &ssh[mm * 64 + dp * 32];
#pragma unroll
            for (int j = 0; j < 32; j++) num1[j] += qv * sr[j];
            if (dp == 0) den1 += qv * zsh[mm];
        }
        __syncthreads();
    }
    // write masked A (aliases qsh/ksh — all mt uses done)
#pragma unroll
    for (int i = 0; i < 8; i++) {
        int c = ty * 8 + i;
#pragma unroll
        for (int j = 0; j < 8; j++) {
            int t = tx * 8 + j;
            Ash[c * ASTR + t] = (t <= c) ? accA[i][j] : 0.f;
        }
    }
    __syncthreads();
    float num2[32];
#pragma unroll
    for (int j = 0; j < 32; j++) num2[j] = 0.f;
    float den2 = 0.f;
    for (int t = 0; t < cCHUNK; t++) {
        float a = Ash[cc * ASTR + t];
        const float* vr = &vsh[t * cDH + dp * 32];
#pragma unroll
        for (int j = 0; j < 32; j++) num2[j] += a * vr[j];
        if (dp == 0) den2 += a;
    }
    if (dp == 0) densh[cc] = den1 + den2;
    __syncthreads();
    float invden = 1.f / (densh[cc] + 1e-6f);
    float* op = o_b + (size_t)(c0 + cc) * cE + dp * 32;
#pragma unroll
    for (int j = 0; j < 32; j += 4)
        *(float4*)&op[j] = make_float4((num1[j] + num2[j]) * invden,
                                       (num1[j + 1] + num2[j + 1]) * invden,
                                       (num1[j + 2] + num2[j + 2]) * invden,
                                       (num1[j + 3] + num2[j + 3]) * invden);
}

// ---------------- host orchestration ----------------
extern "C" void kernel_launch(void* const* d_in, const int* in_sizes, int n_in,
                              void* d_out, int out_size)
{
    const int*   src  = (const int*)d_in[0];
    const float* emb  = (const float*)d_in[2];
    const float* lng  = (const float*)d_in[3];
    const float* lnb  = (const float*)d_in[4];
    const float* Wq   = (const float*)d_in[5];
    const float* Wk   = (const float*)d_in[6];
    const float* Wv   = (const float*)d_in[7];
    const float* Wo   = (const float*)d_in[8];
    const float* ln1g = (const float*)d_in[9];
    const float* ln1b = (const float*)d_in[10];
    const float* W1   = (const float*)d_in[11];
    const float* b1   = (const float*)d_in[12];
    const float* W2   = (const float*)d_in[13];
    const float* b2   = (const float*)d_in[14];
    const float* ln2g = (const float*)d_in[15];
    const float* ln2b = (const float*)d_in[16];
    const float* proj = (const float*)d_in[17];
    const float* fcw  = (const float*)d_in[18];
    const float* fcb  = (const float*)d_in[19];
    float* out = (float*)d_out;

    float* sc = nullptr;
    cudaGetSymbolAddress((void**)&sc, g_scratch);
    float* x    = sc + OFF_X;
    float* h    = sc + OFF_H;
    float* q    = sc + OFF_Q;
    float* k    = sc + OFF_K;
    float* v    = sc + OFF_V;
    float* o    = sc + OFF_O;
    float* ffn  = sc + OFF_FFN;
    float* qf   = sc + OFF_QF;
    float* kf   = sc + OFF_KF;
    float* kd   = sc + OFF_KD;
    float* kvs  = sc + OFF_KV;
    float* zcb  = sc + OFF_ZC;
    float* gmax = sc + OFF_GMAX;

    cudaFuncSetAttribute(attn_out, cudaFuncAttributeMaxDynamicSharedMemorySize, (int)ATT_SMEM_BYTES);
    cudaFuncSetAttribute(feat_q_kernel, cudaFuncAttributeMaxDynamicSharedMemorySize, (int)FEAT_SMEM_BYTES);
    cudaFuncSetAttribute(feat_k1_kernel, cudaFuncAttributeMaxDynamicSharedMemorySize, (int)FEAT_SMEM_BYTES);

    embed_ln_kernel<<<cBS, 256>>>(src, emb, lng, lnb, x);

    dim3 g512(cE / 128, cBS / 128);
    dim3 gF1(4 * cE / 128, cBS / 128);
    dim3 gQKV(12, cBS / 128);
    dim3 gFeat(cS / 16, cBH);
    dim3 gChunk(cNC, cBH);
    dim3 gPfx(cBH, 4);

    for (int l = 0; l < cL; l++) {
        ln_kernel<<<cBS, 256>>>(x, ln1g + (size_t)l * cE, ln1b + (size_t)l * cE, h);
        gemm_qkv<<<gQKV, 256>>>(h, Wq + (size_t)l * cE * cE, Wk + (size_t)l * cE * cE,
                                Wv + (size_t)l * cE * cE, q, k, v);

        const float* pl = proj + (size_t)l * cM * cDH;
        feat_q_kernel<<<gFeat, 256, FEAT_SMEM_BYTES>>>(q, pl, qf);
        init_gmax_kernel<<<1, 1>>>(gmax);
        feat_k1_kernel<<<gFeat, 256, FEAT_SMEM_BYTES>>>(k, pl, kf, kd, gmax);
        feat_k2_kernel<<<4096, 256>>>(kf, kd, gmax);

        attn_chunk_sums<<<gChunk, 256>>>(kf, v, kvs, zcb);
        attn_prefix<<<gPfx, 256>>>(kvs, zcb);
        attn_out<<<gChunk, 256, ATT_SMEM_BYTES>>>(qf, kf, v, kvs, zcb, o);

        gemm_tf32<<<g512, 256>>>(o, Wo + (size_t)l * cE * cE, nullptr, x, x, cE, cE, 0);

        ln_kernel<<<cBS, 256>>>(x, ln2g + (size_t)l * cE, ln2b + (size_t)l * cE, h);
        gemm_tf32<<<gF1, 256>>>(h, W1 + (size_t)l * cE * 4 * cE, b1 + (size_t)l * 4 * cE,
                                nullptr, ffn, 4 * cE, cE, 1);
        gemm_tf32<<<g512, 256>>>(ffn, W2 + (size_t)l * 4 * cE * cE, b2 + (size_t)l * cE,
                                 x, x, cE, 4 * cE, 0);
    }

    gemm_tf32<<<dim3(cV / 128, cBS / 128), 256>>>(x, fcw, fcb, nullptr, out, cV, cE, 0);
}

// round 8
// speedup vs baseline: 6.1850x; 1.0961x over previous
#include <cuda_runtime.h>
#include <cuda_bf16.h>
#include <math.h>
#include <stdint.h>

// ---------------- problem constants ----------------
constexpr int cB = 2, cS = 2048, cV = 32000, cE = 512, cH = 8, cL = 4;
constexpr int cDH = 64, cM = 256, cCHUNK = 128;
constexpr int cBS = cB * cS;                 // 4096 rows
constexpr int cBH = cB * cH;                 // 16
constexpr int cNC = cS / cCHUNK;             // 16 chunks

// ---------------- scratch ----------------
constexpr size_t OFF_X    = 0;
constexpr size_t OFF_H    = OFF_X + (size_t)cBS * cE;
constexpr size_t OFF_Q    = OFF_H + (size_t)cBS * cE;
constexpr size_t OFF_K    = OFF_Q + (size_t)cBS * cE;
constexpr size_t OFF_V    = OFF_K + (size_t)cBS * cE;
constexpr size_t OFF_O    = OFF_V + (size_t)cBS * cE;
constexpr size_t OFF_FFN  = OFF_O + (size_t)cBS * cE;
constexpr size_t OFF_QF   = OFF_FFN + (size_t)cBS * 4 * cE;
constexpr size_t OFF_KF   = OFF_QF + (size_t)cBH * cS * cM;
constexpr size_t OFF_KD   = OFF_KF + (size_t)cBH * cS * cM;
constexpr size_t OFF_KV   = OFF_KD + (size_t)cBH * cS;
constexpr size_t OFF_ZC   = OFF_KV + (size_t)cBH * cNC * cM * cDH;
constexpr size_t OFF_GMAX = OFF_ZC + (size_t)cBH * cNC * cM;
constexpr size_t SCRATCH_FLOATS = OFF_GMAX + 64;

__device__ float g_scratch[SCRATCH_FLOATS];

// ---------------- helpers ----------------
__device__ __forceinline__ void atomicMaxFloat(float* addr, float value) {
    if (value >= 0.f) atomicMax((int*)addr, __float_as_int(value));
    else              atomicMin((unsigned int*)addr, __float_as_uint(value));
}

__device__ __forceinline__ unsigned f2tf32(float x) {
    unsigned r;
    asm("cvt.rna.tf32.f32 %0, %1;" : "=r"(r) : "f"(x));
    return r;
}

__device__ __forceinline__ void mma_tf32(float* c, const unsigned* a, unsigned b0, unsigned b1) {
    asm volatile("mma.sync.aligned.m16n8k8.row.col.f32.tf32.tf32.f32 "
        "{%0,%1,%2,%3}, {%4,%5,%6,%7}, {%8,%9}, {%0,%1,%2,%3};"
        : "+f"(c[0]), "+f"(c[1]), "+f"(c[2]), "+f"(c[3])
        : "r"(a[0]), "r"(a[1]), "r"(a[2]), "r"(a[3]), "r"(b0), "r"(b1));
}

__device__ __forceinline__ void cp16(unsigned dst, const void* src) {
    asm volatile("cp.async.cg.shared.global [%0], [%1], 16;" :: "r"(dst), "l"(src));
}
__device__ __forceinline__ void cp_commit() { asm volatile("cp.async.commit_group;"); }
template<int n> __device__ __forceinline__ void cp_wait() {
    asm volatile("cp.async.wait_group %0;" :: "n"(n));
}

// ---------------- embed + posenc + LN ----------------
__global__ void embed_ln_kernel(const int* __restrict__ src, const float* __restrict__ emb,
                                const float* __restrict__ g, const float* __restrict__ bpar,
                                float* __restrict__ x)
{
    __shared__ float row[cE];
    __shared__ float red[256];
    int r = blockIdx.x;
    int s = r % cS;
    int tid = threadIdx.x;
    int tok = src[r];
    const float kPos = -9.210340371976184f / (float)cE;
    for (int e = tid; e < cE; e += 256) {
        int twoj = e & ~1;
        float div = expf((float)twoj * kPos);
        float ang = (float)s * div;
        float pe = (e & 1) ? cosf(ang) : sinf(ang);
        row[e] = emb[(size_t)tok * cE + e] + pe;
    }
    __syncthreads();
    float a0 = row[tid], a1 = row[tid + 256];
    red[tid] = a0 + a1;
    __syncthreads();
    for (int sft = 128; sft > 0; sft >>= 1) { if (tid < sft) red[tid] += red[tid + sft]; __syncthreads(); }
    float mu = red[0] * (1.f / cE);
    __syncthreads();
    float d0 = a0 - mu, d1 = a1 - mu;
    red[tid] = d0 * d0 + d1 * d1;
    __syncthreads();
    for (int sft = 128; sft > 0; sft >>= 1) { if (tid < sft) red[tid] += red[tid + sft]; __syncthreads(); }
    float rstd = rsqrtf(red[0] * (1.f / cE) + 1e-5f);
    x[(size_t)r * cE + tid]       = d0 * rstd * g[tid]       + bpar[tid];
    x[(size_t)r * cE + tid + 256] = d1 * rstd * g[tid + 256] + bpar[tid + 256];
}

__global__ void ln_kernel(const float* __restrict__ in, const float* __restrict__ g,
                          const float* __restrict__ bpar, float* __restrict__ out)
{
    __shared__ float red[256];
    int r = blockIdx.x;
    int tid = threadIdx.x;
    float a0 = in[(size_t)r * cE + tid];
    float a1 = in[(size_t)r * cE + tid + 256];
    red[tid] = a0 + a1;
    __syncthreads();
    for (int sft = 128; sft > 0; sft >>= 1) { if (tid < sft) red[tid] += red[tid + sft]; __syncthreads(); }
    float mu = red[0] * (1.f / cE);
    __syncthreads();
    float d0 = a0 - mu, d1 = a1 - mu;
    red[tid] = d0 * d0 + d1 * d1;
    __syncthreads();
    for (int sft = 128; sft > 0; sft >>= 1) { if (tid < sft) red[tid] += red[tid + sft]; __syncthreads(); }
    float rstd = rsqrtf(red[0] * (1.f / cE) + 1e-5f);
    out[(size_t)r * cE + tid]       = d0 * rstd * g[tid]       + bpar[tid];
    out[(size_t)r * cE + tid + 256] = d1 * rstd * g[tid + 256] + bpar[tid + 256];
}

// ---------------- TF32 tensor-core GEMM v3: 3-stage cp.async pipeline ----------------
constexpr int AST = 20;    // A smem row stride ([m][k] layout)
constexpr int BST = 136;   // B smem row stride ([k][n] layout)
constexpr int NSTG = 3;
constexpr size_t GEMM_SMEM_BYTES = (size_t)(NSTG * 128 * AST + NSTG * 16 * BST) * 4;  // 56832

__global__ __launch_bounds__(256, 2)
void gemm_tf32(const float* __restrict__ A, const float* __restrict__ Bm,
               const float* __restrict__ bias, const float* __restrict__ res,
               float* __restrict__ C, int N, int K, int act)
{
    extern __shared__ float gsm[];
    float* Asm = gsm;                               // [NSTG][128*AST]
    float* Bsm = gsm + (size_t)NSTG * 128 * AST;    // [NSTG][16*BST]

    int tid = threadIdx.x;
    int warp = tid >> 5, lane = tid & 31;
    int wm = warp >> 2, wn = warp & 3;
    int g = lane >> 2, t4 = lane & 3;
    int row0 = blockIdx.y * 128, col0 = blockIdx.x * 128;

    int arow = tid >> 1, ak = (tid & 1) * 8;
    int brow = tid >> 4, bn = (tid & 15) * 8;

    const float* Ap = A + (size_t)(row0 + arow) * K + ak;
    const float* Bp = Bm + (size_t)brow * N + col0 + bn;
    unsigned aBase = (unsigned)__cvta_generic_to_shared(Asm) + (unsigned)(arow * AST + ak) * 4;
    unsigned bBase = (unsigned)__cvta_generic_to_shared(Bsm) + (unsigned)(brow * BST + bn) * 4;

    int nT = K >> 4;

    auto issue = [&](int t) {
        int s = t % NSTG;
        unsigned ad = aBase + (unsigned)s * (128 * AST * 4);
        const float* ap = Ap + t * 16;
        cp16(ad, ap);
        cp16(ad + 16, ap + 4);
        unsigned bd = bBase + (unsigned)s * (16 * BST * 4);
        const float* bp = Bp + (size_t)(t * 16) * N;
        cp16(bd, bp);
        cp16(bd + 16, bp + 4);
    };

    float acc[4][4][4];
#pragma unroll
    for (int mi = 0; mi < 4; mi++)
#pragma unroll
        for (int ni = 0; ni < 4; ni++)
#pragma unroll
            for (int q = 0; q < 4; q++) acc[mi][ni][q] = 0.f;

    issue(0); cp_commit();
    issue(1); cp_commit();

    for (int t = 0; t < nT; t++) {
        cp_wait<1>();
        __syncthreads();
        if (t + 2 < nT) issue(t + 2);
        cp_commit();
        const float* aS = Asm + (size_t)(t % NSTG) * (128 * AST);
        const float* bS = Bsm + (size_t)(t % NSTG) * (16 * BST);
#pragma unroll
        for (int ks = 0; ks < 16; ks += 8) {
            unsigned af[4][4];
#pragma unroll
            for (int mi = 0; mi < 4; mi++) {
                int m = wm * 64 + mi * 16 + g;
                af[mi][0] = f2tf32(aS[m * AST + ks + t4]);
                af[mi][1] = f2tf32(aS[(m + 8) * AST + ks + t4]);
                af[mi][2] = f2tf32(aS[m * AST + ks + t4 + 4]);
                af[mi][3] = f2tf32(aS[(m + 8) * AST + ks + t4 + 4]);
            }
#pragma unroll
            for (int ni = 0; ni < 4; ni++) {
                int n = wn * 32 + ni * 8 + g;
                unsigned bf0 = f2tf32(bS[(ks + t4) * BST + n]);
                unsigned bf1 = f2tf32(bS[(ks + t4 + 4) * BST + n]);
#pragma unroll
                for (int mi = 0; mi < 4; mi++)
                    mma_tf32(acc[mi][ni], af[mi], bf0, bf1);
            }
        }
    }

#pragma unroll
    for (int mi = 0; mi < 4; mi++) {
#pragma unroll
        for (int ni = 0; ni < 4; ni++) {
            int row = row0 + wm * 64 + mi * 16 + g;
            int col = col0 + wn * 32 + ni * 8 + 2 * t4;
#pragma unroll
            for (int half = 0; half < 2; half++) {
                int r = row + half * 8;
                float v0 = acc[mi][ni][half * 2 + 0];
                float v1 = acc[mi][ni][half * 2 + 1];
                if (bias) { v0 += bias[col]; v1 += bias[col + 1]; }
                if (act) {
                    v0 = 0.5f * v0 * (1.f + erff(v0 * 0.70710678118654752f));
                    v1 = 0.5f * v1 * (1.f + erff(v1 * 0.70710678118654752f));
                }
                if (res) {
                    v0 += res[(size_t)r * N + col];
                    v1 += res[(size_t)r * N + col + 1];
                }
                *(float2*)&C[(size_t)r * N + col] = make_float2(v0, v1);
            }
        }
    }
}

// fused QKV with same v3 pipeline: grid.x in [0,12): sel = bx/4
__global__ __launch_bounds__(256, 2)
void gemm_qkv(const float* __restrict__ A, const float* __restrict__ Bq,
              const float* __restrict__ Bk, const float* __restrict__ Bv,
              float* __restrict__ Cq, float* __restrict__ Ck, float* __restrict__ Cv)
{
    constexpr int N = cE, K = cE;
    extern __shared__ float gsm[];
    float* Asm = gsm;
    float* Bsm = gsm + (size_t)NSTG * 128 * AST;

    int tid = threadIdx.x;
    int warp = tid >> 5, lane = tid & 31;
    int wm = warp >> 2, wn = warp & 3;
    int g = lane >> 2, t4 = lane & 3;
    int bx = blockIdx.x;
    int sel = bx >> 2;
    const float* Bm = sel == 0 ? Bq : (sel == 1 ? Bk : Bv);
    float* C = sel == 0 ? Cq : (sel == 1 ? Ck : Cv);
    int row0 = blockIdx.y * 128, col0 = (bx & 3) * 128;

    int arow = tid >> 1, ak = (tid & 1) * 8;
    int brow = tid >> 4, bn = (tid & 15) * 8;

    const float* Ap = A + (size_t)(row0 + arow) * K + ak;
    const float* Bp = Bm + (size_t)brow * N + col0 + bn;
    unsigned aBase = (unsigned)__cvta_generic_to_shared(Asm) + (unsigned)(arow * AST + ak) * 4;
    unsigned bBase = (unsigned)__cvta_generic_to_shared(Bsm) + (unsigned)(brow * BST + bn) * 4;

    int nT = K >> 4;

    auto issue = [&](int t) {
        int s = t % NSTG;
        unsigned ad = aBase + (unsigned)s * (128 * AST * 4);
        const float* ap = Ap + t * 16;
        cp16(ad, ap);
        cp16(ad + 16, ap + 4);
        unsigned bd = bBase + (unsigned)s * (16 * BST * 4);
        const float* bp = Bp + (size_t)(t * 16) * N;
        cp16(bd, bp);
        cp16(bd + 16, bp + 4);
    };

    float acc[4][4][4];
#pragma unroll
    for (int mi = 0; mi < 4; mi++)
#pragma unroll
        for (int ni = 0; ni < 4; ni++)
#pragma unroll
            for (int q = 0; q < 4; q++) acc[mi][ni][q] = 0.f;

    issue(0); cp_commit();
    issue(1); cp_commit();

    for (int t = 0; t < nT; t++) {
        cp_wait<1>();
        __syncthreads();
        if (t + 2 < nT) issue(t + 2);
        cp_commit();
        const float* aS = Asm + (size_t)(t % NSTG) * (128 * AST);
        const float* bS = Bsm + (size_t)(t % NSTG) * (16 * BST);
#pragma unroll
        for (int ks = 0; ks < 16; ks += 8) {
            unsigned af[4][4];
#pragma unroll
            for (int mi = 0; mi < 4; mi++) {
                int m = wm * 64 + mi * 16 + g;
                af[mi][0] = f2tf32(aS[m * AST + ks + t4]);
                af[mi][1] = f2tf32(aS[(m + 8) * AST + ks + t4]);
                af[mi][2] = f2tf32(aS[m * AST + ks + t4 + 4]);
                af[mi][3] = f2tf32(aS[(m + 8) * AST + ks + t4 + 4]);
            }
#pragma unroll
            for (int ni = 0; ni < 4; ni++) {
                int n = wn * 32 + ni * 8 + g;
                unsigned bf0 = f2tf32(bS[(ks + t4) * BST + n]);
                unsigned bf1 = f2tf32(bS[(ks + t4 + 4) * BST + n]);
#pragma unroll
                for (int mi = 0; mi < 4; mi++)
                    mma_tf32(acc[mi][ni], af[mi], bf0, bf1);
            }
        }
    }

#pragma unroll
    for (int mi = 0; mi < 4; mi++) {
#pragma unroll
        for (int ni = 0; ni < 4; ni++) {
            int row = row0 + wm * 64 + mi * 16 + g;
            int col = col0 + wn * 32 + ni * 8 + 2 * t4;
#pragma unroll
            for (int half = 0; half < 2; half++) {
                int r = row + half * 8;
                *(float2*)&C[(size_t)r * N + col] =
                    make_float2(acc[mi][ni][half * 2 + 0], acc[mi][ni][half * 2 + 1]);
            }
        }
    }
}

// ---------------- fused FAVOR+ features (q + k in one kernel) ----------------
constexpr int FPST = 68;  // proj smem stride
constexpr size_t FEAT2_FLOATS = (size_t)cM * FPST + 2 * 16 * 64 + 32 + 16 * 8 + 8 + 16;
constexpr size_t FEAT2_BYTES = FEAT2_FLOATS * 4;

__global__ void feat_qk_kernel(const float* __restrict__ q, const float* __restrict__ k,
                               const float* __restrict__ proj, float* __restrict__ qf,
                               float* __restrict__ kf, float* __restrict__ kdiag,
                               float* __restrict__ gmax)
{
    extern __shared__ float fsm[];
    float* psh    = fsm;                     // [256][68]
    float* xq     = psh + (size_t)cM * FPST; // [16][64]
    float* xk     = xq + 16 * 64;            // [16][64]
    float* ssq    = xk + 16 * 64;            // [32]: 0..15 q, 16..31 k
    float* wred   = ssq + 32;                // [16][8]
    float* kred   = wred + 128;              // [8]
    float* rowmax = kred + 8;                // [16]

    int s0 = blockIdx.x * 16;
    int bh = blockIdx.y;
    int b = bh / cH, h = bh % cH;
    int tid = threadIdx.x;

    for (int i = tid; i < cM * cDH; i += 256)
        psh[(i >> 6) * FPST + (i & 63)] = proj[i];
    for (int i = tid; i < 16 * 64; i += 256) {
        int s = i >> 6, d = i & 63;
        size_t gi = (size_t)(b * cS + s0 + s) * cE + h * cDH + d;
        xq[i] = q[gi];
        xk[i] = k[gi];
    }
    __syncthreads();
    if (tid < 32) {
        const float* xp = (tid < 16) ? xq : xk;
        int s = tid & 15;
        float acc = 0.f;
#pragma unroll
        for (int d = 0; d < 64; d += 4) {
            float4 xv = *(const float4*)&xp[s * 64 + d];
            acc += xv.x * xv.x + xv.y * xv.y + xv.z * xv.z + xv.w * xv.w;
        }
        ssq[tid] = acc;
    }
    const float dn = 0.35355339059327373f;
    int m = tid;
    float xdq[16], xdk[16];
#pragma unroll
    for (int s = 0; s < 16; s++) {
        float dq = 0.f, dk = 0.f;
#pragma unroll
        for (int d = 0; d < 64; d += 4) {
            float4 p  = *(const float4*)&psh[m * FPST + d];
            float4 aq = *(const float4*)&xq[s * 64 + d];
            float4 ck = *(const float4*)&xk[s * 64 + d];
            dq += p.x * aq.x + p.y * aq.y + p.z * aq.z + p.w * aq.w;
            dk += p.x * ck.x + p.y * ck.y + p.z * ck.z + p.w * ck.w;
        }
        xdq[s] = dq * dn;
        xdk[s] = dk * dn;
    }
    int lane = tid & 31, warp = tid >> 5;
#pragma unroll
    for (int s = 0; s < 16; s++) {
        float mx = xdq[s];
#pragma unroll
        for (int sft = 16; sft > 0; sft >>= 1) mx = fmaxf(mx, __shfl_xor_sync(0xffffffff, mx, sft));
        if (lane == 0) wred[s * 8 + warp] = mx;
    }
    float tmax = xdk[0];
#pragma unroll
    for (int s = 1; s < 16; s++) tmax = fmaxf(tmax, xdk[s]);
#pragma unroll
    for (int sft = 16; sft > 0; sft >>= 1) tmax = fmaxf(tmax, __shfl_xor_sync(0xffffffff, tmax, sft));
    if (lane == 0) kred[warp] = tmax;
    __syncthreads();
    if (tid < 16) {
        float mx = wred[tid * 8];
#pragma unroll
        for (int w = 1; w < 8; w++) mx = fmaxf(mx, wred[tid * 8 + w]);
        rowmax[tid] = mx;
        kdiag[(size_t)bh * cS + s0 + tid] = 0.5f * ssq[16 + tid] * dn * dn;
    }
    if (tid == 0) {
        float mx = kred[0];
#pragma unroll
        for (int w = 1; w < 8; w++) mx = fmaxf(mx, kred[w]);
        atomicMaxFloat(gmax, mx);
    }
    __syncthreads();
#pragma unroll
    for (int s = 0; s < 16; s++) {
        float diag = 0.5f * ssq[s] * dn * dn;
        size_t oi = ((size_t)bh * cS + s0 + s) * cM + m;
        qf[oi] = 0.0625f * (expf(xdq[s] - diag - rowmax[s]) + 1e-4f);
        kf[oi] = xdk[s];
    }
}

__global__ void init_gmax_kernel(float* gmax) { *gmax = -3.4e38f; }

__global__ void feat_k2_kernel(float* __restrict__ kf, const float* __restrict__ kdiag,
                               const float* __restrict__ gmax)
{
    float gm = *gmax;
    size_t total = (size_t)cBH * cS * cM;
    for (size_t i = (size_t)blockIdx.x * blockDim.x + threadIdx.x; i < total;
         i += (size_t)gridDim.x * blockDim.x) {
        kf[i] = 0.0625f * (expf(kf[i] - kdiag[i >> 8] - gm) + 1e-4f);
    }
}

// ---------------- attention phase A: per-chunk state sums ----------------
__global__ void attn_chunk_sums(const float* __restrict__ kf, const float* __restrict__ v,
                                float* __restrict__ kvsum, float* __restrict__ zc)
{
    __shared__ float vsh[cCHUNK * cDH];
    int ch = blockIdx.x, bh = blockIdx.y;
    int b = bh / cH, h = bh % cH;
    int tid = threadIdx.x;
    int c0 = ch * cCHUNK;
    const float* v_b = v + (size_t)b * cS * cE + h * cDH;
    for (int i = tid; i < cCHUNK * cDH; i += 256) {
        int c = i >> 6, d = i & 63;
        vsh[i] = v_b[(size_t)(c0 + c) * cE + d];
    }
    __syncthreads();
    int m = tid;
    float acc[cDH];
#pragma unroll
    for (int d = 0; d < cDH; d++) acc[d] = 0.f;
    float zacc = 0.f;
    const float* kf_b = kf + ((size_t)bh * cS + c0) * cM + m;
    for (int i = 0; i < cCHUNK; i++) {
        float kv = kf_b[(size_t)i * cM];
        zacc += kv;
        const float4* vr = (const float4*)&vsh[i * cDH];
#pragma unroll
        for (int j = 0; j < 16; j++) {
            float4 vv = vr[j];
            acc[j * 4 + 0] += kv * vv.x;
            acc[j * 4 + 1] += kv * vv.y;
            acc[j * 4 + 2] += kv * vv.z;
            acc[j * 4 + 3] += kv * vv.w;
        }
    }
    float* outp = kvsum + (((size_t)bh * cNC + ch) * cM + m) * cDH;
#pragma unroll
    for (int d = 0; d < cDH; d += 4)
        *(float4*)&outp[d] = make_float4(acc[d], acc[d + 1], acc[d + 2], acc[d + 3]);
    zc[((size_t)bh * cNC + ch) * cM + m] = zacc;
}

// ---------------- attention phase B: exclusive prefix over chunks ----------------
__global__ void attn_prefix(float* __restrict__ kvsum, float* __restrict__ zc)
{
    int bh = blockIdx.x, ds = blockIdx.y;
    int m = threadIdx.x;
    int d0 = ds * 16;
    float carry[16];
#pragma unroll
    for (int j = 0; j < 16; j++) carry[j] = 0.f;
    float zcarry = 0.f;
    for (int c = 0; c < cNC; c++) {
        float* p = kvsum + (((size_t)bh * cNC + c) * cM + m) * cDH + d0;
#pragma unroll
        for (int j = 0; j < 16; j += 4) {
            float4 t = *(float4*)&p[j];
            *(float4*)&p[j] = make_float4(carry[j], carry[j + 1], carry[j + 2], carry[j + 3]);
            carry[j] += t.x; carry[j + 1] += t.y; carry[j + 2] += t.z; carry[j + 3] += t.w;
        }
        if (ds == 0) {
            float* zp = zc + ((size_t)bh * cNC + c) * cM + m;
            float t = *zp;
            *zp = zcarry;
            zcarry += t;
        }
    }
}

// ---------------- attention phase C: per-chunk output ----------------
constexpr int ASTR = cCHUNK + 1;  // 129
constexpr size_t ATT_SMEM_FLOATS =
    (size_t)cCHUNK * cDH + cCHUNK + (size_t)cCHUNK * ASTR + 64 * 64 + 64;
constexpr size_t ATT_SMEM_BYTES = ATT_SMEM_FLOATS * 4;

__global__ void attn_out(const float* __restrict__ qf, const float* __restrict__ kf,
                         const float* __restrict__ v, const float* __restrict__ kvsum,
                         const float* __restrict__ zc, float* __restrict__ o)
{
    extern __shared__ float sm[];
    float* vsh   = sm;                              // [128][64]
    float* densh = vsh + (size_t)cCHUNK * cDH;      // [128]
    float* uni   = densh + cCHUNK;
    float* qsh   = uni;                             // [64][129]
    float* ksh   = uni + (size_t)64 * ASTR;         // [64][129]
    float* Ash   = uni;                             // [128][129] (aliases after mt loop)
    float* ssh   = uni + (size_t)cCHUNK * ASTR;     // [64][64]
    float* zsh   = ssh + 64 * 64;                   // [64]

    int ch = blockIdx.x, bh = blockIdx.y;
    int b = bh / cH, h = bh % cH;
    int tid = threadIdx.x;
    int tx = tid & 15, ty = tid >> 4;
    int cc = tid & 127, dp = tid >> 7;
    int c0 = ch * cCHUNK;

    const float* qf_b = qf + (size_t)bh * cS * cM;
    const float* kf_b = kf + (size_t)bh * cS * cM;
    const float* v_b  = v + (size_t)b * cS * cE + h * cDH;
    const float* Sp   = kvsum + ((size_t)bh * cNC + ch) * cM * cDH;
    const float* zp   = zc + ((size_t)bh * cNC + ch) * cM;
    float*       o_b  = o + (size_t)b * cS * cE + h * cDH;

    for (int i = tid; i < cCHUNK * cDH; i += 256) {
        int c = i >> 6, d = i & 63;
        vsh[i] = v_b[(size_t)(c0 + c) * cE + d];
    }

    float accA[8][8];
#pragma unroll
    for (int i = 0; i < 8; i++)
#pragma unroll
        for (int j = 0; j < 8; j++) accA[i][j] = 0.f;
    float num1[32];
#pragma unroll
    for (int j = 0; j < 32; j++) num1[j] = 0.f;
    float den1 = 0.f;
    __syncthreads();

    for (int mt = 0; mt < cM / 64; mt++) {
        for (int i = tid; i < 64 * cCHUNK; i += 256) {
            int mm = i & 63;
            int c = i >> 6;
            size_t gidx = (size_t)(c0 + c) * cM + mt * 64 + mm;
            qsh[mm * ASTR + c] = qf_b[gidx];
            ksh[mm * ASTR + c] = kf_b[gidx];
        }
        for (int i = tid; i < 64 * 64; i += 256) ssh[i] = Sp[(size_t)(mt * 64) * cDH + i];
        if (tid < 64) zsh[tid] = zp[mt * 64 + tid];
        __syncthreads();
        for (int mm = 0; mm < 64; mm++) {
            float fq[8], fk[8];
#pragma unroll
            for (int i = 0; i < 8; i++) fq[i] = qsh[mm * ASTR + ty * 8 + i];
#pragma unroll
            for (int j = 0; j < 8; j++) fk[j] = ksh[mm * ASTR + tx * 8 + j];
#pragma unroll
            for (int i = 0; i < 8; i++)
#pragma unroll
                for (int j = 0; j < 8; j++) accA[i][j] += fq[i] * fk[j];
        }
        for (int mm = 0; mm < 64; mm++) {
            float qv = qsh[mm * ASTR + cc];
            const float4* sr = (const float4*)&ssh[mm * 64 + dp * 32];
#pragma unroll
            for (int j = 0; j < 8; j++) {
                float4 sv = sr[j];
                num1[j * 4 + 0] += qv * sv.x;
                num1[j * 4 + 1] += qv * sv.y;
                num1[j * 4 + 2] += qv * sv.z;
                num1[j * 4 + 3] += qv * sv.w;
            }
            if (dp == 0) den1 += qv * zsh[mm];
        }
        __syncthreads();
    }
#pragma unroll
    for (int i = 0; i < 8; i++) {
        int c = ty * 8 + i;
#pragma unroll
        for (int j = 0; j < 8; j++) {
            int t = tx * 8 + j;
            Ash[c * ASTR + t] = (t <= c) ? accA[i][j] : 0.f;
        }
    }
    __syncthreads();
    float num2[32];
#pragma unroll
    for (int j = 0; j < 32; j++) num2[j] = 0.f;
    float den2 = 0.f;
    for (int t = 0; t < cCHUNK; t++) {
        float a = Ash[cc * ASTR + t];
        const float4* vr = (const float4*)&vsh[t * cDH + dp * 32];
#pragma unroll
        for (int j = 0; j < 8; j++) {
            float4 vv = vr[j];
            num2[j * 4 + 0] += a * vv.x;
            num2[j * 4 + 1] += a * vv.y;
            num2[j * 4 + 2] += a * vv.z;
            num2[j * 4 + 3] += a * vv.w;
        }
        if (dp == 0) den2 += a;
    }
    if (dp == 0) densh[cc] = den1 + den2;
    __syncthreads();
    float invden = 1.f / (densh[cc] + 1e-6f);
    float* op = o_b + (size_t)(c0 + cc) * cE + dp * 32;
#pragma unroll
    for (int j = 0; j < 32; j += 4)
        *(float4*)&op[j] = make_float4((num1[j] + num2[j]) * invden,
                                       (num1[j + 1] + num2[j + 1]) * invden,
                                       (num1[j + 2] + num2[j + 2]) * invden,
                                       (num1[j + 3] + num2[j + 3]) * invden);
}

// ---------------- host orchestration ----------------
extern "C" void kernel_launch(void* const* d_in, const int* in_sizes, int n_in,
                              void* d_out, int out_size)
{
    const int*   src  = (const int*)d_in[0];
    const float* emb  = (const float*)d_in[2];
    const float* lng  = (const float*)d_in[3];
    const float* lnb  = (const float*)d_in[4];
    const float* Wq   = (const float*)d_in[5];
    const float* Wk   = (const float*)d_in[6];
    const float* Wv   = (const float*)d_in[7];
    const float* Wo   = (const float*)d_in[8];
    const float* ln1g = (const float*)d_in[9];
    const float* ln1b = (const float*)d_in[10];
    const float* W1   = (const float*)d_in[11];
    const float* b1   = (const float*)d_in[12];
    const float* W2   = (const float*)d_in[13];
    const float* b2   = (const float*)d_in[14];
    const float* ln2g = (const float*)d_in[15];
    const float* ln2b = (const float*)d_in[16];
    const float* proj = (const float*)d_in[17];
    const float* fcw  = (const float*)d_in[18];
    const float* fcb  = (const float*)d_in[19];
    float* out = (float*)d_out;

    float* sc = nullptr;
    cudaGetSymbolAddress((void**)&sc, g_scratch);
    float* x    = sc + OFF_X;
    float* h    = sc + OFF_H;
    float* q    = sc + OFF_Q;
    float* k    = sc + OFF_K;
    float* v    = sc + OFF_V;
    float* o    = sc + OFF_O;
    float* ffn  = sc + OFF_FFN;
    float* qf   = sc + OFF_QF;
    float* kf   = sc + OFF_KF;
    float* kd   = sc + OFF_KD;
    float* kvs  = sc + OFF_KV;
    float* zcb  = sc + OFF_ZC;
    float* gmax = sc + OFF_GMAX;

    cudaFuncSetAttribute(gemm_tf32, cudaFuncAttributeMaxDynamicSharedMemorySize, (int)GEMM_SMEM_BYTES);
    cudaFuncSetAttribute(gemm_qkv, cudaFuncAttributeMaxDynamicSharedMemorySize, (int)GEMM_SMEM_BYTES);
    cudaFuncSetAttribute(attn_out, cudaFuncAttributeMaxDynamicSharedMemorySize, (int)ATT_SMEM_BYTES);
    cudaFuncSetAttribute(feat_qk_kernel, cudaFuncAttributeMaxDynamicSharedMemorySize, (int)FEAT2_BYTES);

    embed_ln_kernel<<<cBS, 256>>>(src, emb, lng, lnb, x);

    dim3 g512(cE / 128, cBS / 128);
    dim3 gF1(4 * cE / 128, cBS / 128);
    dim3 gQKV(12, cBS / 128);
    dim3 gFeat(cS / 16, cBH);
    dim3 gChunk(cNC, cBH);
    dim3 gPfx(cBH, 4);

    for (int l = 0; l < cL; l++) {
        ln_kernel<<<cBS, 256>>>(x, ln1g + (size_t)l * cE, ln1b + (size_t)l * cE, h);
        gemm_qkv<<<gQKV, 256, GEMM_SMEM_BYTES>>>(h, Wq + (size_t)l * cE * cE,
                                                 Wk + (size_t)l * cE * cE,
                                                 Wv + (size_t)l * cE * cE, q, k, v);

        const float* pl = proj + (size_t)l * cM * cDH;
        init_gmax_kernel<<<1, 1>>>(gmax);
        feat_qk_kernel<<<gFeat, 256, FEAT2_BYTES>>>(q, k, pl, qf, kf, kd, gmax);
        feat_k2_kernel<<<4096, 256>>>(kf, kd, gmax);

        attn_chunk_sums<<<gChunk, 256>>>(kf, v, kvs, zcb);
        attn_prefix<<<gPfx, 256>>>(kvs, zcb);
        attn_out<<<gChunk, 256, ATT_SMEM_BYTES>>>(qf, kf, v, kvs, zcb, o);

        gemm_tf32<<<g512, 256, GEMM_SMEM_BYTES>>>(o, Wo + (size_t)l * cE * cE, nullptr, x, x, cE, cE, 0);

        ln_kernel<<<cBS, 256>>>(x, ln2g + (size_t)l * cE, ln2b + (size_t)l * cE, h);
        gemm_tf32<<<gF1, 256, GEMM_SMEM_BYTES>>>(h, W1 + (size_t)l * cE * 4 * cE,
                                                 b1 + (size_t)l * 4 * cE, nullptr, ffn, 4 * cE, cE, 1);
        gemm_tf32<<<g512, 256, GEMM_SMEM_BYTES>>>(ffn, W2 + (size_t)l * 4 * cE * cE,
                                                  b2 + (size_t)l * cE, x, x, cE, 4 * cE, 0);
    }

    gemm_tf32<<<dim3(cV / 128, cBS / 128), 256, GEMM_SMEM_BYTES>>>(x, fcw, fcb, nullptr, out, cV, cE, 0);
}

// round 9
// speedup vs baseline: 8.4954x; 1.3736x over previous
#include <cuda_runtime.h>
#include <cuda_bf16.h>
#include <cuda_fp16.h>
#include <math.h>
#include <stdint.h>

// ---------------- problem constants ----------------
constexpr int cB = 2, cS = 2048, cV = 32000, cE = 512, cH = 8, cL = 4;
constexpr int cDH = 64, cM = 256, cCHUNK = 128;
constexpr int cBS = cB * cS;                 // 4096 rows
constexpr int cBH = cB * cH;                 // 16
constexpr int cNC = cS / cCHUNK;             // 16 chunks

// ---------------- float scratch ----------------
constexpr size_t OFF_X    = 0;
constexpr size_t OFF_Q    = OFF_X + (size_t)cBS * cE;
constexpr size_t OFF_K    = OFF_Q + (size_t)cBS * cE;
constexpr size_t OFF_V    = OFF_K + (size_t)cBS * cE;
constexpr size_t OFF_QF   = OFF_V + (size_t)cBS * cE;
constexpr size_t OFF_KF   = OFF_QF + (size_t)cBH * cS * cM;
constexpr size_t OFF_KD   = OFF_KF + (size_t)cBH * cS * cM;
constexpr size_t OFF_KV   = OFF_KD + (size_t)cBH * cS;
constexpr size_t OFF_ZC   = OFF_KV + (size_t)cBH * cNC * cM * cDH;
constexpr size_t OFF_GMAX = OFF_ZC + (size_t)cBH * cNC * cM;
constexpr size_t SCRATCH_FLOATS = OFF_GMAX + 64;

__device__ float g_scratch[SCRATCH_FLOATS];

// ---------------- half scratch ----------------
constexpr size_t HOFF_H   = 0;
constexpr size_t HOFF_O   = HOFF_H + (size_t)cBS * cE;
constexpr size_t HOFF_FFN = HOFF_O + (size_t)cBS * cE;
constexpr size_t HOFF_XH  = HOFF_FFN + (size_t)cBS * 4 * cE;
constexpr size_t HOFF_WQ  = HOFF_XH + (size_t)cBS * cE;
constexpr size_t HOFF_WK  = HOFF_WQ + (size_t)cL * cE * cE;
constexpr size_t HOFF_WV  = HOFF_WK + (size_t)cL * cE * cE;
constexpr size_t HOFF_WO  = HOFF_WV + (size_t)cL * cE * cE;
constexpr size_t HOFF_W1  = HOFF_WO + (size_t)cL * cE * cE;
constexpr size_t HOFF_W2  = HOFF_W1 + (size_t)cL * cE * 4 * cE;
constexpr size_t HOFF_FCW = HOFF_W2 + (size_t)cL * cE * 4 * cE;
constexpr size_t SCRATCH_HALVES = HOFF_FCW + (size_t)cE * cV;

__device__ __half g_scratch_h[SCRATCH_HALVES];

// ---------------- helpers ----------------
__device__ __forceinline__ void atomicMaxFloat(float* addr, float value) {
    if (value >= 0.f) atomicMax((int*)addr, __float_as_int(value));
    else              atomicMin((unsigned int*)addr, __float_as_uint(value));
}

__device__ __forceinline__ void mma_f16(float* c, const unsigned* a, unsigned b0, unsigned b1) {
    asm volatile("mma.sync.aligned.m16n8k16.row.col.f32.f16.f16.f32 "
        "{%0,%1,%2,%3}, {%4,%5,%6,%7}, {%8,%9}, {%0,%1,%2,%3};"
        : "+f"(c[0]), "+f"(c[1]), "+f"(c[2]), "+f"(c[3])
        : "r"(a[0]), "r"(a[1]), "r"(a[2]), "r"(a[3]), "r"(b0), "r"(b1));
}

__device__ __forceinline__ void ldsm_x4(unsigned& r0, unsigned& r1, unsigned& r2, unsigned& r3,
                                        unsigned addr) {
    asm volatile("ldmatrix.sync.aligned.m8n8.x4.shared.b16 {%0,%1,%2,%3}, [%4];"
        : "=r"(r0), "=r"(r1), "=r"(r2), "=r"(r3) : "r"(addr));
}
__device__ __forceinline__ void ldsm_x2t(unsigned& r0, unsigned& r1, unsigned addr) {
    asm volatile("ldmatrix.sync.aligned.m8n8.x2.trans.shared.b16 {%0,%1}, [%2];"
        : "=r"(r0), "=r"(r1) : "r"(addr));
}

__device__ __forceinline__ void cp16(unsigned dst, const void* src) {
    asm volatile("cp.async.cg.shared.global [%0], [%1], 16;" :: "r"(dst), "l"(src));
}
__device__ __forceinline__ void cp_commit() { asm volatile("cp.async.commit_group;"); }
template<int n> __device__ __forceinline__ void cp_wait() {
    asm volatile("cp.async.wait_group %0;" :: "n"(n));
}

// ---------------- fp32 -> fp16 convert ----------------
__global__ void f2h_kernel(const float* __restrict__ in, __half* __restrict__ out, int n4)
{
    for (int i = blockIdx.x * blockDim.x + threadIdx.x; i < n4; i += gridDim.x * blockDim.x) {
        float4 v = *(const float4*)(in + (size_t)i * 4);
        __half2 h0 = __floats2half2_rn(v.x, v.y);
        __half2 h1 = __floats2half2_rn(v.z, v.w);
        *(__half2*)(out + (size_t)i * 4)     = h0;
        *(__half2*)(out + (size_t)i * 4 + 2) = h1;
    }
}

// ---------------- embed + posenc + LN (fp32 out) ----------------
__global__ void embed_ln_kernel(const int* __restrict__ src, const float* __restrict__ emb,
                                const float* __restrict__ g, const float* __restrict__ bpar,
                                float* __restrict__ x)
{
    __shared__ float row[cE];
    __shared__ float red[256];
    int r = blockIdx.x;
    int s = r % cS;
    int tid = threadIdx.x;
    int tok = src[r];
    const float kPos = -9.210340371976184f / (float)cE;
    for (int e = tid; e < cE; e += 256) {
        int twoj = e & ~1;
        float div = expf((float)twoj * kPos);
        float ang = (float)s * div;
        float pe = (e & 1) ? cosf(ang) : sinf(ang);
        row[e] = emb[(size_t)tok * cE + e] + pe;
    }
    __syncthreads();
    float a0 = row[tid], a1 = row[tid + 256];
    red[tid] = a0 + a1;
    __syncthreads();
    for (int sft = 128; sft > 0; sft >>= 1) { if (tid < sft) red[tid] += red[tid + sft]; __syncthreads(); }
    float mu = red[0] * (1.f / cE);
    __syncthreads();
    float d0 = a0 - mu, d1 = a1 - mu;
    red[tid] = d0 * d0 + d1 * d1;
    __syncthreads();
    for (int sft = 128; sft > 0; sft >>= 1) { if (tid < sft) red[tid] += red[tid + sft]; __syncthreads(); }
    float rstd = rsqrtf(red[0] * (1.f / cE) + 1e-5f);
    x[(size_t)r * cE + tid]       = d0 * rstd * g[tid]       + bpar[tid];
    x[(size_t)r * cE + tid + 256] = d1 * rstd * g[tid + 256] + bpar[tid + 256];
}

// LN producing fp16 (GEMM A operand)
__global__ void ln_kernel_h(const float* __restrict__ in, const float* __restrict__ g,
                            const float* __restrict__ bpar, __half* __restrict__ out)
{
    __shared__ float red[256];
    int r = blockIdx.x;
    int tid = threadIdx.x;
    float a0 = in[(size_t)r * cE + tid];
    float a1 = in[(size_t)r * cE + tid + 256];
    red[tid] = a0 + a1;
    __syncthreads();
    for (int sft = 128; sft > 0; sft >>= 1) { if (tid < sft) red[tid] += red[tid + sft]; __syncthreads(); }
    float mu = red[0] * (1.f / cE);
    __syncthreads();
    float d0 = a0 - mu, d1 = a1 - mu;
    red[tid] = d0 * d0 + d1 * d1;
    __syncthreads();
    for (int sft = 128; sft > 0; sft >>= 1) { if (tid < sft) red[tid] += red[tid + sft]; __syncthreads(); }
    float rstd = rsqrtf(red[0] * (1.f / cE) + 1e-5f);
    out[(size_t)r * cE + tid]       = __float2half(d0 * rstd * g[tid]       + bpar[tid]);
    out[(size_t)r * cE + tid + 256] = __float2half(d1 * rstd * g[tid + 256] + bpar[tid + 256]);
}

// ---------------- FP16 tensor-core GEMM: 4-stage cp.async + ldmatrix ----------------
constexpr int AST2 = 24;    // A smem row stride in halves ([m][k], 16 data + 8 pad)
constexpr int BST2 = 136;   // B smem row stride in halves ([k][n], 128 data + 8 pad)
constexpr int HSTG = 4;
constexpr int ASZ = 128 * AST2;   // halves per A stage
constexpr int BSZ = 16 * BST2;    // halves per B stage
constexpr size_t GEMM_SMEM_BYTES = (size_t)HSTG * (ASZ + BSZ) * 2;  // 42112

// C (fp32, optional) and Ch (fp16, optional). act=1 -> exact GELU after bias.
__global__ __launch_bounds__(256, 2)
void gemm_f16(const __half* __restrict__ A, const __half* __restrict__ Bm,
              const float* __restrict__ bias, const float* __restrict__ res,
              float* __restrict__ C, __half* __restrict__ Ch, int N, int K, int act)
{
    extern __shared__ __half hsm[];
    __half* Asm = hsm;                               // [HSTG][ASZ]
    __half* Bsm = hsm + (size_t)HSTG * ASZ;          // [HSTG][BSZ]

    int tid = threadIdx.x;
    int warp = tid >> 5, lane = tid & 31;
    int wm = warp >> 2, wn = warp & 3;
    int g = lane >> 2, t4 = lane & 3;
    int row0 = blockIdx.y * 128, col0 = blockIdx.x * 128;

    int arow = tid >> 1, ac8 = (tid & 1) * 8;
    int brow = tid >> 4, bc8 = (tid & 15) * 8;

    const __half* Ap = A + (size_t)(row0 + arow) * K + ac8;
    const __half* Bp = Bm + (size_t)brow * N + col0 + bc8;
    unsigned aBase = (unsigned)__cvta_generic_to_shared(Asm) + (unsigned)(arow * AST2 + ac8) * 2;
    unsigned bBase = (unsigned)__cvta_generic_to_shared(Bsm) + (unsigned)(brow * BST2 + bc8) * 2;
    unsigned aLds = (unsigned)__cvta_generic_to_shared(Asm);
    unsigned bLds = (unsigned)__cvta_generic_to_shared(Bsm);

    int nT = K >> 4;

    auto issue = [&](int t) {
        int s = t & (HSTG - 1);
        cp16(aBase + (unsigned)s * (ASZ * 2), Ap + (size_t)t * 16);
        cp16(bBase + (unsigned)s * (BSZ * 2), Bp + (size_t)(t * 16) * N);
    };

    float acc[4][4][4];
#pragma unroll
    for (int mi = 0; mi < 4; mi++)
#pragma unroll
        for (int ni = 0; ni < 4; ni++)
#pragma unroll
            for (int q = 0; q < 4; q++) acc[mi][ni][q] = 0.f;

    issue(0); cp_commit();
    issue(1); cp_commit();
    issue(2); cp_commit();

    // ldmatrix address components
    int aRowSel = lane & 15;            // row within 16-row fragment
    int aColSel = (lane >> 4) * 8;      // 0 or 8 (k offset)
    int bRowSel = lane & 15;            // k row

    for (int t = 0; t < nT; t++) {
        cp_wait<2>();
        __syncthreads();
        if (t + 3 < nT) issue(t + 3);
        cp_commit();
        int s = t & (HSTG - 1);
        unsigned aS = aLds + (unsigned)s * (ASZ * 2);
        unsigned bS = bLds + (unsigned)s * (BSZ * 2);

        unsigned afr[4][4];
#pragma unroll
        for (int mi = 0; mi < 4; mi++) {
            int row = wm * 64 + mi * 16 + aRowSel;
            ldsm_x4(afr[mi][0], afr[mi][1], afr[mi][2], afr[mi][3],
                    aS + (unsigned)(row * AST2 + aColSel) * 2);
        }
        unsigned bfr[4][2];
#pragma unroll
        for (int ni = 0; ni < 4; ni++) {
            int n = wn * 32 + ni * 8;
            ldsm_x2t(bfr[ni][0], bfr[ni][1], bS + (unsigned)(bRowSel * BST2 + n) * 2);
        }
#pragma unroll
        for (int ni = 0; ni < 4; ni++)
#pragma unroll
            for (int mi = 0; mi < 4; mi++)
                mma_f16(acc[mi][ni], afr[mi], bfr[ni][0], bfr[ni][1]);
    }

#pragma unroll
    for (int mi = 0; mi < 4; mi++) {
#pragma unroll
        for (int ni = 0; ni < 4; ni++) {
            int row = row0 + wm * 64 + mi * 16 + g;
            int col = col0 + wn * 32 + ni * 8 + 2 * t4;
#pragma unroll
            for (int half_ = 0; half_ < 2; half_++) {
                int r = row + half_ * 8;
                float v0 = acc[mi][ni][half_ * 2 + 0];
                float v1 = acc[mi][ni][half_ * 2 + 1];
                if (bias) { v0 += bias[col]; v1 += bias[col + 1]; }
                if (act) {
                    v0 = 0.5f * v0 * (1.f + erff(v0 * 0.70710678118654752f));
                    v1 = 0.5f * v1 * (1.f + erff(v1 * 0.70710678118654752f));
                }
                if (res) {
                    v0 += res[(size_t)r * N + col];
                    v1 += res[(size_t)r * N + col + 1];
                }
                if (C)  *(float2*)&C[(size_t)r * N + col] = make_float2(v0, v1);
                if (Ch) *(__half2*)&Ch[(size_t)r * N + col] = __floats2half2_rn(v0, v1);
            }
        }
    }
}

// fused QKV: grid.x in [0,12): sel = bx/4, fp32 outputs
__global__ __launch_bounds__(256, 2)
void gemm_qkv(const __half* __restrict__ A, const __half* __restrict__ Bq,
              const __half* __restrict__ Bk, const __half* __restrict__ Bv,
              float* __restrict__ Cq, float* __restrict__ Ck, float* __restrict__ Cv)
{
    constexpr int N = cE, K = cE;
    extern __shared__ __half hsm[];
    __half* Asm = hsm;
    __half* Bsm = hsm + (size_t)HSTG * ASZ;

    int tid = threadIdx.x;
    int warp = tid >> 5, lane = tid & 31;
    int wm = warp >> 2, wn = warp & 3;
    int g = lane >> 2, t4 = lane & 3;
    int bx = blockIdx.x;
    int sel = bx >> 2;
    const __half* Bm = sel == 0 ? Bq : (sel == 1 ? Bk : Bv);
    float* C = sel == 0 ? Cq : (sel == 1 ? Ck : Cv);
    int row0 = blockIdx.y * 128, col0 = (bx & 3) * 128;

    int arow = tid >> 1, ac8 = (tid & 1) * 8;
    int brow = tid >> 4, bc8 = (tid & 15) * 8;

    const __half* Ap = A + (size_t)(row0 + arow) * K + ac8;
    const __half* Bp = Bm + (size_t)brow * N + col0 + bc8;
    unsigned aBase = (unsigned)__cvta_generic_to_shared(Asm) + (unsigned)(arow * AST2 + ac8) * 2;
    unsigned bBase = (unsigned)__cvta_generic_to_shared(Bsm) + (unsigned)(brow * BST2 + bc8) * 2;
    unsigned aLds = (unsigned)__cvta_generic_to_shared(Asm);
    unsigned bLds = (unsigned)__cvta_generic_to_shared(Bsm);

    int nT = K >> 4;

    auto issue = [&](int t) {
        int s = t & (HSTG - 1);
        cp16(aBase + (unsigned)s * (ASZ * 2), Ap + (size_t)t * 16);
        cp16(bBase + (unsigned)s * (BSZ * 2), Bp + (size_t)(t * 16) * N);
    };

    float acc[4][4][4];
#pragma unroll
    for (int mi = 0; mi < 4; mi++)
#pragma unroll
        for (int ni = 0; ni < 4; ni++)
#pragma unroll
            for (int q = 0; q < 4; q++) acc[mi][ni][q] = 0.f;

    issue(0); cp_commit();
    issue(1); cp_commit();
    issue(2); cp_commit();

    int aRowSel = lane & 15;
    int aColSel = (lane >> 4) * 8;
    int bRowSel = lane & 15;

    for (int t = 0; t < nT; t++) {
        cp_wait<2>();
        __syncthreads();
        if (t + 3 < nT) issue(t + 3);
        cp_commit();
        int s = t & (HSTG - 1);
        unsigned aS = aLds + (unsigned)s * (ASZ * 2);
        unsigned bS = bLds + (unsigned)s * (BSZ * 2);

        unsigned afr[4][4];
#pragma unroll
        for (int mi = 0; mi < 4; mi++) {
            int row = wm * 64 + mi * 16 + aRowSel;
            ldsm_x4(afr[mi][0], afr[mi][1], afr[mi][2], afr[mi][3],
                    aS + (unsigned)(row * AST2 + aColSel) * 2);
        }
        unsigned bfr[4][2];
#pragma unroll
        for (int ni = 0; ni < 4; ni++) {
            int n = wn * 32 + ni * 8;
            ldsm_x2t(bfr[ni][0], bfr[ni][1], bS + (unsigned)(bRowSel * BST2 + n) * 2);
        }
#pragma unroll
        for (int ni = 0; ni < 4; ni++)
#pragma unroll
            for (int mi = 0; mi < 4; mi++)
                mma_f16(acc[mi][ni], afr[mi], bfr[ni][0], bfr[ni][1]);
    }

#pragma unroll
    for (int mi = 0; mi < 4; mi++) {
#pragma unroll
        for (int ni = 0; ni < 4; ni++) {
            int row = row0 + wm * 64 + mi * 16 + g;
            int col = col0 + wn * 32 + ni * 8 + 2 * t4;
#pragma unroll
            for (int half_ = 0; half_ < 2; half_++) {
                int r = row + half_ * 8;
                *(float2*)&C[(size_t)r * N + col] =
                    make_float2(acc[mi][ni][half_ * 2 + 0], acc[mi][ni][half_ * 2 + 1]);
            }
        }
    }
}

// ---------------- fused FAVOR+ features (q + k in one kernel) ----------------
constexpr int FPST = 68;
constexpr size_t FEAT2_FLOATS = (size_t)cM * FPST + 2 * 16 * 64 + 32 + 16 * 8 + 8 + 16;
constexpr size_t FEAT2_BYTES = FEAT2_FLOATS * 4;

__global__ void feat_qk_kernel(const float* __restrict__ q, const float* __restrict__ k,
                               const float* __restrict__ proj, float* __restrict__ qf,
                               float* __restrict__ kf, float* __restrict__ kdiag,
                               float* __restrict__ gmax)
{
    extern __shared__ float fsm[];
    float* psh    = fsm;                     // [256][68]
    float* xq     = psh + (size_t)cM * FPST; // [16][64]
    float* xk     = xq + 16 * 64;            // [16][64]
    float* ssq    = xk + 16 * 64;            // [32]
    float* wred   = ssq + 32;                // [16][8]
    float* kred   = wred + 128;              // [8]
    float* rowmax = kred + 8;                // [16]

    int s0 = blockIdx.x * 16;
    int bh = blockIdx.y;
    int b = bh / cH, h = bh % cH;
    int tid = threadIdx.x;

    for (int i = tid; i < cM * cDH; i += 256)
        psh[(i >> 6) * FPST + (i & 63)] = proj[i];
    for (int i = tid; i < 16 * 64; i += 256) {
        int s = i >> 6, d = i & 63;
        size_t gi = (size_t)(b * cS + s0 + s) * cE + h * cDH + d;
        xq[i] = q[gi];
        xk[i] = k[gi];
    }
    __syncthreads();
    if (tid < 32) {
        const float* xp = (tid < 16) ? xq : xk;
        int s = tid & 15;
        float acc = 0.f;
#pragma unroll
        for (int d = 0; d < 64; d += 4) {
            float4 xv = *(const float4*)&xp[s * 64 + d];
            acc += xv.x * xv.x + xv.y * xv.y + xv.z * xv.z + xv.w * xv.w;
        }
        ssq[tid] = acc;
    }
    const float dn = 0.35355339059327373f;
    int m = tid;
    float xdq[16], xdk[16];
#pragma unroll
    for (int s = 0; s < 16; s++) {
        float dq = 0.f, dk = 0.f;
#pragma unroll
        for (int d = 0; d < 64; d += 4) {
            float4 p  = *(const float4*)&psh[m * FPST + d];
            float4 aq = *(const float4*)&xq[s * 64 + d];
            float4 ck = *(const float4*)&xk[s * 64 + d];
            dq += p.x * aq.x + p.y * aq.y + p.z * aq.z + p.w * aq.w;
            dk += p.x * ck.x + p.y * ck.y + p.z * ck.z + p.w * ck.w;
        }
        xdq[s] = dq * dn;
        xdk[s] = dk * dn;
    }
    int lane = tid & 31, warp = tid >> 5;
#pragma unroll
    for (int s = 0; s < 16; s++) {
        float mx = xdq[s];
#pragma unroll
        for (int sft = 16; sft > 0; sft >>= 1) mx = fmaxf(mx, __shfl_xor_sync(0xffffffff, mx, sft));
        if (lane == 0) wred[s * 8 + warp] = mx;
    }
    float tmax = xdk[0];
#pragma unroll
    for (int s = 1; s < 16; s++) tmax = fmaxf(tmax, xdk[s]);
#pragma unroll
    for (int sft = 16; sft > 0; sft >>= 1) tmax = fmaxf(tmax, __shfl_xor_sync(0xffffffff, tmax, sft));
    if (lane == 0) kred[warp] = tmax;
    __syncthreads();
    if (tid < 16) {
        float mx = wred[tid * 8];
#pragma unroll
        for (int w = 1; w < 8; w++) mx = fmaxf(mx, wred[tid * 8 + w]);
        rowmax[tid] = mx;
        kdiag[(size_t)bh * cS + s0 + tid] = 0.5f * ssq[16 + tid] * dn * dn;
    }
    if (tid == 0) {
        float mx = kred[0];
#pragma unroll
        for (int w = 1; w < 8; w++) mx = fmaxf(mx, kred[w]);
        atomicMaxFloat(gmax, mx);
    }
    __syncthreads();
#pragma unroll
    for (int s = 0; s < 16; s++) {
        float diag = 0.5f * ssq[s] * dn * dn;
        size_t oi = ((size_t)bh * cS + s0 + s) * cM + m;
        qf[oi] = 0.0625f * (expf(xdq[s] - diag - rowmax[s]) + 1e-4f);
        kf[oi] = xdk[s];
    }
}

__global__ void init_gmax_kernel(float* gmax) { *gmax = -3.4e38f; }

__global__ void feat_k2_kernel(float* __restrict__ kf, const float* __restrict__ kdiag,
                               const float* __restrict__ gmax)
{
    float gm = *gmax;
    size_t total = (size_t)cBH * cS * cM;
    for (size_t i = (size_t)blockIdx.x * blockDim.x + threadIdx.x; i < total;
         i += (size_t)gridDim.x * blockDim.x) {
        kf[i] = 0.0625f * (expf(kf[i] - kdiag[i >> 8] - gm) + 1e-4f);
    }
}

// ---------------- attention phase A: per-chunk state sums ----------------
__global__ void attn_chunk_sums(const float* __restrict__ kf, const float* __restrict__ v,
                                float* __restrict__ kvsum, float* __restrict__ zc)
{
    __shared__ float vsh[cCHUNK * cDH];
    int ch = blockIdx.x, bh = blockIdx.y;
    int b = bh / cH, h = bh % cH;
    int tid = threadIdx.x;
    int c0 = ch * cCHUNK;
    const float* v_b = v + (size_t)b * cS * cE + h * cDH;
    for (int i = tid; i < cCHUNK * cDH; i += 256) {
        int c = i >> 6, d = i & 63;
        vsh[i] = v_b[(size_t)(c0 + c) * cE + d];
    }
    __syncthreads();
    int m = tid;
    float acc[cDH];
#pragma unroll
    for (int d = 0; d < cDH; d++) acc[d] = 0.f;
    float zacc = 0.f;
    const float* kf_b = kf + ((size_t)bh * cS + c0) * cM + m;
    for (int i = 0; i < cCHUNK; i++) {
        float kv = kf_b[(size_t)i * cM];
        zacc += kv;
        const float4* vr = (const float4*)&vsh[i * cDH];
#pragma unroll
        for (int j = 0; j < 16; j++) {
            float4 vv = vr[j];
            acc[j * 4 + 0] += kv * vv.x;
            acc[j * 4 + 1] += kv * vv.y;
            acc[j * 4 + 2] += kv * vv.z;
            acc[j * 4 + 3] += kv * vv.w;
        }
    }
    float* outp = kvsum + (((size_t)bh * cNC + ch) * cM + m) * cDH;
#pragma unroll
    for (int d = 0; d < cDH; d += 4)
        *(float4*)&outp[d] = make_float4(acc[d], acc[d + 1], acc[d + 2], acc[d + 3]);
    zc[((size_t)bh * cNC + ch) * cM + m] = zacc;
}

// ---------------- attention phase B: exclusive prefix over chunks ----------------
__global__ void attn_prefix(float* __restrict__ kvsum, float* __restrict__ zc)
{
    int bh = blockIdx.x, ds = blockIdx.y;
    int m = threadIdx.x;
    int d0 = ds * 16;
    float carry[16];
#pragma unroll
    for (int j = 0; j < 16; j++) carry[j] = 0.f;
    float zcarry = 0.f;
    for (int c = 0; c < cNC; c++) {
        float* p = kvsum + (((size_t)bh * cNC + c) * cM + m) * cDH + d0;
#pragma unroll
        for (int j = 0; j < 16; j += 4) {
            float4 t = *(float4*)&p[j];
            *(float4*)&p[j] = make_float4(carry[j], carry[j + 1], carry[j + 2], carry[j + 3]);
            carry[j] += t.x; carry[j + 1] += t.y; carry[j + 2] += t.z; carry[j + 3] += t.w;
        }
        if (ds == 0) {
            float* zp = zc + ((size_t)bh * cNC + c) * cM + m;
            float t = *zp;
            *zp = zcarry;
            zcarry += t;
        }
    }
}

// ---------------- attention phase C: per-chunk output (fp16 out) ----------------
constexpr int ASTR = cCHUNK + 1;  // 129
constexpr size_t ATT_SMEM_FLOATS =
    (size_t)cCHUNK * cDH + cCHUNK + (size_t)cCHUNK * ASTR + 64 * 64 + 64;
constexpr size_t ATT_SMEM_BYTES = ATT_SMEM_FLOATS * 4;

__global__ void attn_out(const float* __restrict__ qf, const float* __restrict__ kf,
                         const float* __restrict__ v, const float* __restrict__ kvsum,
                         const float* __restrict__ zc, __half* __restrict__ o)
{
    extern __shared__ float sm[];
    float* vsh   = sm;                              // [128][64]
    float* densh = vsh + (size_t)cCHUNK * cDH;      // [128]
    float* uni   = densh + cCHUNK;
    float* qsh   = uni;                             // [64][129]
    float* ksh   = uni + (size_t)64 * ASTR;         // [64][129]
    float* Ash   = uni;                             // [128][129] (aliases after mt loop)
    float* ssh   = uni + (size_t)cCHUNK * ASTR;     // [64][64]
    float* zsh   = ssh + 64 * 64;                   // [64]

    int ch = blockIdx.x, bh = blockIdx.y;
    int b = bh / cH, h = bh % cH;
    int tid = threadIdx.x;
    int tx = tid & 15, ty = tid >> 4;
    int cc = tid & 127, dp = tid >> 7;
    int c0 = ch * cCHUNK;

    const float* qf_b = qf + (size_t)bh * cS * cM;
    const float* kf_b = kf + (size_t)bh * cS * cM;
    const float* v_b  = v + (size_t)b * cS * cE + h * cDH;
    const float* Sp   = kvsum + ((size_t)bh * cNC + ch) * cM * cDH;
    const float* zp   = zc + ((size_t)bh * cNC + ch) * cM;
    __half*      o_b  = o + (size_t)b * cS * cE + h * cDH;

    for (int i = tid; i < cCHUNK * cDH; i += 256) {
        int c = i >> 6, d = i & 63;
        vsh[i] = v_b[(size_t)(c0 + c) * cE + d];
    }

    float accA[8][8];
#pragma unroll
    for (int i = 0; i < 8; i++)
#pragma unroll
        for (int j = 0; j < 8; j++) accA[i][j] = 0.f;
    float num1[32];
#pragma unroll
    for (int j = 0; j < 32; j++) num1[j] = 0.f;
    float den1 = 0.f;
    __syncthreads();

    for (int mt = 0; mt < cM / 64; mt++) {
        for (int i = tid; i < 64 * cCHUNK; i += 256) {
            int mm = i & 63;
            int c = i >> 6;
            size_t gidx = (size_t)(c0 + c) * cM + mt * 64 + mm;
            qsh[mm * ASTR + c] = qf_b[gidx];
            ksh[mm * ASTR + c] = kf_b[gidx];
        }
        for (int i = tid; i < 64 * 64; i += 256) ssh[i] = Sp[(size_t)(mt * 64) * cDH + i];
        if (tid < 64) zsh[tid] = zp[mt * 64 + tid];
        __syncthreads();
        for (int mm = 0; mm < 64; mm++) {
            float fq[8], fk[8];
#pragma unroll
            for (int i = 0; i < 8; i++) fq[i] = qsh[mm * ASTR + ty * 8 + i];
#pragma unroll
            for (int j = 0; j < 8; j++) fk[j] = ksh[mm * ASTR + tx * 8 + j];
#pragma unroll
            for (int i = 0; i < 8; i++)
#pragma unroll
                for (int j = 0; j < 8; j++) accA[i][j] += fq[i] * fk[j];
        }
        for (int mm = 0; mm < 64; mm++) {
            float qv = qsh[mm * ASTR + cc];
            const float4* sr = (const float4*)&ssh[mm * 64 + dp * 32];
#pragma unroll
            for (int j = 0; j < 8; j++) {
                float4 sv = sr[j];
                num1[j * 4 + 0] += qv * sv.x;
                num1[j * 4 + 1] += qv * sv.y;
                num1[j * 4 + 2] += qv * sv.z;
                num1[j * 4 + 3] += qv * sv.w;
            }
            if (dp == 0) den1 += qv * zsh[mm];
        }
        __syncthreads();
    }
#pragma unroll
    for (int i = 0; i < 8; i++) {
        int c = ty * 8 + i;
#pragma unroll
        for (int j = 0; j < 8; j++) {
            int t = tx * 8 + j;
            Ash[c * ASTR + t] = (t <= c) ? accA[i][j] : 0.f;
        }
    }
    __syncthreads();
    float num2[32];
#pragma unroll
    for (int j = 0; j < 32; j++) num2[j] = 0.f;
    float den2 = 0.f;
    for (int t = 0; t < cCHUNK; t++) {
        float a = Ash[cc * ASTR + t];
        const float4* vr = (const float4*)&vsh[t * cDH + dp * 32];
#pragma unroll
        for (int j = 0; j < 8; j++) {
            float4 vv = vr[j];
            num2[j * 4 + 0] += a * vv.x;
            num2[j * 4 + 1] += a * vv.y;
            num2[j * 4 + 2] += a * vv.z;
            num2[j * 4 + 3] += a * vv.w;
        }
        if (dp == 0) den2 += a;
    }
    if (dp == 0) densh[cc] = den1 + den2;
    __syncthreads();
    float invden = 1.f / (densh[cc] + 1e-6f);
    __half* op = o_b + (size_t)(c0 + cc) * cE + dp * 32;
#pragma unroll
    for (int j = 0; j < 32; j += 2) {
        *(__half2*)&op[j] = __floats2half2_rn((num1[j] + num2[j]) * invden,
                                              (num1[j + 1] + num2[j + 1]) * invden);
    }
}

// ---------------- host orchestration ----------------
extern "C" void kernel_launch(void* const* d_in, const int* in_sizes, int n_in,
                              void* d_out, int out_size)
{
    const int*   src  = (const int*)d_in[0];
    const float* emb  = (const float*)d_in[2];
    const float* lng  = (const float*)d_in[3];
    const float* lnb  = (const float*)d_in[4];
    const float* Wq   = (const float*)d_in[5];
    const float* Wk   = (const float*)d_in[6];
    const float* Wv   = (const float*)d_in[7];
    const float* Wo   = (const float*)d_in[8];
    const float* ln1g = (const float*)d_in[9];
    const float* ln1b = (const float*)d_in[10];
    const float* W1   = (const float*)d_in[11];
    const float* b1   = (const float*)d_in[12];
    const float* W2   = (const float*)d_in[13];
    const float* b2   = (const float*)d_in[14];
    const float* ln2g = (const float*)d_in[15];
    const float* ln2b = (const float*)d_in[16];
    const float* proj = (const float*)d_in[17];
    const float* fcw  = (const float*)d_in[18];
    const float* fcb  = (const float*)d_in[19];
    float* out = (float*)d_out;

    float* sc = nullptr;
    cudaGetSymbolAddress((void**)&sc, g_scratch);
    __half* sh = nullptr;
    cudaGetSymbolAddress((void**)&sh, g_scratch_h);

    float* x    = sc + OFF_X;
    float* q    = sc + OFF_Q;
    float* k    = sc + OFF_K;
    float* v    = sc + OFF_V;
    float* qf   = sc + OFF_QF;
    float* kf   = sc + OFF_KF;
    float* kd   = sc + OFF_KD;
    float* kvs  = sc + OFF_KV;
    float* zcb  = sc + OFF_ZC;
    float* gmax = sc + OFF_GMAX;

    __half* hH   = sh + HOFF_H;
    __half* oH   = sh + HOFF_O;
    __half* ffnH = sh + HOFF_FFN;
    __half* xH   = sh + HOFF_XH;
    __half* WqH  = sh + HOFF_WQ;
    __half* WkH  = sh + HOFF_WK;
    __half* WvH  = sh + HOFF_WV;
    __half* WoH  = sh + HOFF_WO;
    __half* W1H  = sh + HOFF_W1;
    __half* W2H  = sh + HOFF_W2;
    __half* fcwH = sh + HOFF_FCW;

    cudaFuncSetAttribute(gemm_f16, cudaFuncAttributeMaxDynamicSharedMemorySize, (int)GEMM_SMEM_BYTES);
    cudaFuncSetAttribute(gemm_qkv, cudaFuncAttributeMaxDynamicSharedMemorySize, (int)GEMM_SMEM_BYTES);
    cudaFuncSetAttribute(attn_out, cudaFuncAttributeMaxDynamicSharedMemorySize, (int)ATT_SMEM_BYTES);
    cudaFuncSetAttribute(feat_qk_kernel, cudaFuncAttributeMaxDynamicSharedMemorySize, (int)FEAT2_BYTES);

    // weight conversion (once per launch)
    int nWsm = cL * cE * cE / 4;           // 262144
    int nWff = cL * cE * 4 * cE / 4;       // 1048576
    int nFcw = cE * cV / 4;                // 4096000
    f2h_kernel<<<512, 256>>>(Wq, WqH, nWsm);
    f2h_kernel<<<512, 256>>>(Wk, WkH, nWsm);
    f2h_kernel<<<512, 256>>>(Wv, WvH, nWsm);
    f2h_kernel<<<512, 256>>>(Wo, WoH, nWsm);
    f2h_kernel<<<1024, 256>>>(W1, W1H, nWff);
    f2h_kernel<<<1024, 256>>>(W2, W2H, nWff);
    f2h_kernel<<<2048, 256>>>(fcw, fcwH, nFcw);

    embed_ln_kernel<<<cBS, 256>>>(src, emb, lng, lnb, x);

    dim3 g512(cE / 128, cBS / 128);
    dim3 gF1(4 * cE / 128, cBS / 128);
    dim3 gQKV(12, cBS / 128);
    dim3 gFeat(cS / 16, cBH);
    dim3 gChunk(cNC, cBH);
    dim3 gPfx(cBH, 4);

    for (int l = 0; l < cL; l++) {
        ln_kernel_h<<<cBS, 256>>>(x, ln1g + (size_t)l * cE, ln1b + (size_t)l * cE, hH);
        gemm_qkv<<<gQKV, 256, GEMM_SMEM_BYTES>>>(hH, WqH + (size_t)l * cE * cE,
                                                 WkH + (size_t)l * cE * cE,
                                                 WvH + (size_t)l * cE * cE, q, k, v);

        const float* pl = proj + (size_t)l * cM * cDH;
        init_gmax_kernel<<<1, 1>>>(gmax);
        feat_qk_kernel<<<gFeat, 256, FEAT2_BYTES>>>(q, k, pl, qf, kf, kd, gmax);
        feat_k2_kernel<<<4096, 256>>>(kf, kd, gmax);

        attn_chunk_sums<<<gChunk, 256>>>(kf, v, kvs, zcb);
        attn_prefix<<<gPfx, 256>>>(kvs, zcb);
        attn_out<<<gChunk, 256, ATT_SMEM_BYTES>>>(qf, kf, v, kvs, zcb, oH);

        // x += o @ Wo  (fp32 out to x)
        gemm_f16<<<g512, 256, GEMM_SMEM_BYTES>>>(oH, WoH + (size_t)l * cE * cE,
                                                 nullptr, x, x, nullptr, cE, cE, 0);

        ln_kernel_h<<<cBS, 256>>>(x, ln2g + (size_t)l * cE, ln2b + (size_t)l * cE, hH);
        // ffn = gelu(h @ W1 + b1)  (fp16 out)
        gemm_f16<<<gF1, 256, GEMM_SMEM_BYTES>>>(hH, W1H + (size_t)l * cE * 4 * cE,
                                                b1 + (size_t)l * 4 * cE, nullptr,
                                                nullptr, ffnH, 4 * cE, cE, 1);
        // x = x + ffn @ W2 + b2  (fp32 out to x, fp16 shadow xH)
        gemm_f16<<<g512, 256, GEMM_SMEM_BYTES>>>(ffnH, W2H + (size_t)l * cE * 4 * cE,
                                                 b2 + (size_t)l * cE, x, x, xH, cE, 4 * cE, 0);
    }

    // out = x @ fc_w + fc_b
    gemm_f16<<<dim3(cV / 128, cBS / 128), 256, GEMM_SMEM_BYTES>>>(
        xH, fcwH, fcb, nullptr, out, nullptr, cV, cE, 0);
}

// round 10
// speedup vs baseline: 10.6257x; 1.2508x over previous
#include <cuda_runtime.h>
#include <cuda_bf16.h>
#include <cuda_fp16.h>
#include <math.h>
#include <stdint.h>

// ---------------- problem constants ----------------
constexpr int cB = 2, cS = 2048, cV = 32000, cE = 512, cH = 8, cL = 4;
constexpr int cDH = 64, cM = 256, cCHUNK = 128;
constexpr int cBS = cB * cS;                 // 4096 rows
constexpr int cBH = cB * cH;                 // 16
constexpr int cNC = cS / cCHUNK;             // 16 chunks

// ---------------- float scratch ----------------
constexpr size_t OFF_X    = 0;
constexpr size_t OFF_Q    = OFF_X + (size_t)cBS * cE;
constexpr size_t OFF_K    = OFF_Q + (size_t)cBS * cE;
constexpr size_t OFF_KF   = OFF_K + (size_t)cBS * cE;              // raw xd
constexpr size_t OFF_KD   = OFF_KF + (size_t)cBH * cS * cM;
constexpr size_t OFF_KV   = OFF_KD + (size_t)cBH * cS;
constexpr size_t OFF_ZC   = OFF_KV + (size_t)cBH * cNC * cM * cDH;
constexpr size_t OFF_GMAX = OFF_ZC + (size_t)cBH * cNC * cM;
constexpr size_t SCRATCH_FLOATS = OFF_GMAX + 64;

__device__ float g_scratch[SCRATCH_FLOATS];

// ---------------- half scratch ----------------
constexpr size_t HOFF_H   = 0;
constexpr size_t HOFF_O   = HOFF_H + (size_t)cBS * cE;
constexpr size_t HOFF_FFN = HOFF_O + (size_t)cBS * cE;
constexpr size_t HOFF_XH  = HOFF_FFN + (size_t)cBS * 4 * cE;
constexpr size_t HOFF_VH  = HOFF_XH + (size_t)cBS * cE;
constexpr size_t HOFF_QFH = HOFF_VH + (size_t)cBS * cE;
constexpr size_t HOFF_KFH = HOFF_QFH + (size_t)cBH * cS * cM;
constexpr size_t HOFF_SPH = HOFF_KFH + (size_t)cBH * cS * cM;      // [bh][c][m][72]
constexpr size_t HOFF_WQ  = HOFF_SPH + (size_t)cBH * cNC * cM * 72;
constexpr size_t HOFF_WK  = HOFF_WQ + (size_t)cL * cE * cE;
constexpr size_t HOFF_WV  = HOFF_WK + (size_t)cL * cE * cE;
constexpr size_t HOFF_WO  = HOFF_WV + (size_t)cL * cE * cE;
constexpr size_t HOFF_W1  = HOFF_WO + (size_t)cL * cE * cE;
constexpr size_t HOFF_W2  = HOFF_W1 + (size_t)cL * cE * 4 * cE;
constexpr size_t HOFF_FCW = HOFF_W2 + (size_t)cL * cE * 4 * cE;
constexpr size_t SCRATCH_HALVES = HOFF_FCW + (size_t)cE * cV;

__device__ __half g_scratch_h[SCRATCH_HALVES];

// ---------------- helpers ----------------
__device__ __forceinline__ void atomicMaxFloat(float* addr, float value) {
    if (value >= 0.f) atomicMax((int*)addr, __float_as_int(value));
    else              atomicMin((unsigned int*)addr, __float_as_uint(value));
}

__device__ __forceinline__ void mma_f16(float* c, const unsigned* a, unsigned b0, unsigned b1) {
    asm volatile("mma.sync.aligned.m16n8k16.row.col.f32.f16.f16.f32 "
        "{%0,%1,%2,%3}, {%4,%5,%6,%7}, {%8,%9}, {%0,%1,%2,%3};"
        : "+f"(c[0]), "+f"(c[1]), "+f"(c[2]), "+f"(c[3])
        : "r"(a[0]), "r"(a[1]), "r"(a[2]), "r"(a[3]), "r"(b0), "r"(b1));
}

__device__ __forceinline__ void ldsm_x4(unsigned& r0, unsigned& r1, unsigned& r2, unsigned& r3,
                                        unsigned addr) {
    asm volatile("ldmatrix.sync.aligned.m8n8.x4.shared.b16 {%0,%1,%2,%3}, [%4];"
        : "=r"(r0), "=r"(r1), "=r"(r2), "=r"(r3) : "r"(addr));
}
__device__ __forceinline__ void ldsm_x4t(unsigned& r0, unsigned& r1, unsigned& r2, unsigned& r3,
                                         unsigned addr) {
    asm volatile("ldmatrix.sync.aligned.m8n8.x4.trans.shared.b16 {%0,%1,%2,%3}, [%4];"
        : "=r"(r0), "=r"(r1), "=r"(r2), "=r"(r3) : "r"(addr));
}
__device__ __forceinline__ void ldsm_x2t(unsigned& r0, unsigned& r1, unsigned addr) {
    asm volatile("ldmatrix.sync.aligned.m8n8.x2.trans.shared.b16 {%0,%1}, [%2];"
        : "=r"(r0), "=r"(r1) : "r"(addr));
}

__device__ __forceinline__ void cp16(unsigned dst, const void* src) {
    asm volatile("cp.async.cg.shared.global [%0], [%1], 16;" :: "r"(dst), "l"(src));
}
__device__ __forceinline__ void cp_commit() { asm volatile("cp.async.commit_group;"); }
template<int n> __device__ __forceinline__ void cp_wait() {
    asm volatile("cp.async.wait_group %0;" :: "n"(n));
}

// ---------------- fp32 -> fp16 convert ----------------
__global__ void f2h_kernel(const float* __restrict__ in, __half* __restrict__ out, int n4)
{
    for (int i = blockIdx.x * blockDim.x + threadIdx.x; i < n4; i += gridDim.x * blockDim.x) {
        float4 v = *(const float4*)(in + (size_t)i * 4);
        *(__half2*)(out + (size_t)i * 4)     = __floats2half2_rn(v.x, v.y);
        *(__half2*)(out + (size_t)i * 4 + 2) = __floats2half2_rn(v.z, v.w);
    }
}

// ---------------- embed + posenc + LN (fp32 out) ----------------
__global__ void embed_ln_kernel(const int* __restrict__ src, const float* __restrict__ emb,
                                const float* __restrict__ g, const float* __restrict__ bpar,
                                float* __restrict__ x)
{
    __shared__ float row[cE];
    __shared__ float red[256];
    int r = blockIdx.x;
    int s = r % cS;
    int tid = threadIdx.x;
    int tok = src[r];
    const float kPos = -9.210340371976184f / (float)cE;
    for (int e = tid; e < cE; e += 256) {
        int twoj = e & ~1;
        float div = expf((float)twoj * kPos);
        float ang = (float)s * div;
        float pe = (e & 1) ? cosf(ang) : sinf(ang);
        row[e] = emb[(size_t)tok * cE + e] + pe;
    }
    __syncthreads();
    float a0 = row[tid], a1 = row[tid + 256];
    red[tid] = a0 + a1;
    __syncthreads();
    for (int sft = 128; sft > 0; sft >>= 1) { if (tid < sft) red[tid] += red[tid + sft]; __syncthreads(); }
    float mu = red[0] * (1.f / cE);
    __syncthreads();
    float d0 = a0 - mu, d1 = a1 - mu;
    red[tid] = d0 * d0 + d1 * d1;
    __syncthreads();
    for (int sft = 128; sft > 0; sft >>= 1) { if (tid < sft) red[tid] += red[tid + sft]; __syncthreads(); }
    float rstd = rsqrtf(red[0] * (1.f / cE) + 1e-5f);
    x[(size_t)r * cE + tid]       = d0 * rstd * g[tid]       + bpar[tid];
    x[(size_t)r * cE + tid + 256] = d1 * rstd * g[tid + 256] + bpar[tid + 256];
}

// LN producing fp16; optionally initializes gmax (one thread)
__global__ void ln_kernel_h(const float* __restrict__ in, const float* __restrict__ g,
                            const float* __restrict__ bpar, __half* __restrict__ out,
                            float* gmax_init)
{
    __shared__ float red[256];
    int r = blockIdx.x;
    int tid = threadIdx.x;
    if (gmax_init && r == 0 && tid == 0) *gmax_init = -3.4e38f;
    float a0 = in[(size_t)r * cE + tid];
    float a1 = in[(size_t)r * cE + tid + 256];
    red[tid] = a0 + a1;
    __syncthreads();
    for (int sft = 128; sft > 0; sft >>= 1) { if (tid < sft) red[tid] += red[tid + sft]; __syncthreads(); }
    float mu = red[0] * (1.f / cE);
    __syncthreads();
    float d0 = a0 - mu, d1 = a1 - mu;
    red[tid] = d0 * d0 + d1 * d1;
    __syncthreads();
    for (int sft = 128; sft > 0; sft >>= 1) { if (tid < sft) red[tid] += red[tid + sft]; __syncthreads(); }
    float rstd = rsqrtf(red[0] * (1.f / cE) + 1e-5f);
    out[(size_t)r * cE + tid]       = __float2half(d0 * rstd * g[tid]       + bpar[tid]);
    out[(size_t)r * cE + tid + 256] = __float2half(d1 * rstd * g[tid + 256] + bpar[tid + 256]);
}

// ---------------- FP16 tensor-core GEMM: 4-stage cp.async + ldmatrix ----------------
constexpr int AST2 = 24;
constexpr int BST2 = 136;
constexpr int HSTG = 4;
constexpr int ASZ = 128 * AST2;
constexpr int BSZ = 16 * BST2;
constexpr size_t GEMM_SMEM_BYTES = (size_t)HSTG * (ASZ + BSZ) * 2;

__global__ __launch_bounds__(256, 2)
void gemm_f16(const __half* __restrict__ A, const __half* __restrict__ Bm,
              const float* __restrict__ bias, const float* __restrict__ res,
              float* __restrict__ C, __half* __restrict__ Ch, int N, int K, int act)
{
    extern __shared__ __half hsm[];
    __half* Asm = hsm;
    __half* Bsm = hsm + (size_t)HSTG * ASZ;

    int tid = threadIdx.x;
    int warp = tid >> 5, lane = tid & 31;
    int wm = warp >> 2, wn = warp & 3;
    int g = lane >> 2, t4 = lane & 3;
    int row0 = blockIdx.y * 128, col0 = blockIdx.x * 128;

    int arow = tid >> 1, ac8 = (tid & 1) * 8;
    int brow = tid >> 4, bc8 = (tid & 15) * 8;

    const __half* Ap = A + (size_t)(row0 + arow) * K + ac8;
    const __half* Bp = Bm + (size_t)brow * N + col0 + bc8;
    unsigned aBase = (unsigned)__cvta_generic_to_shared(Asm) + (unsigned)(arow * AST2 + ac8) * 2;
    unsigned bBase = (unsigned)__cvta_generic_to_shared(Bsm) + (unsigned)(brow * BST2 + bc8) * 2;
    unsigned aLds = (unsigned)__cvta_generic_to_shared(Asm);
    unsigned bLds = (unsigned)__cvta_generic_to_shared(Bsm);

    int nT = K >> 4;

    auto issue = [&](int t) {
        int s = t & (HSTG - 1);
        cp16(aBase + (unsigned)s * (ASZ * 2), Ap + (size_t)t * 16);
        cp16(bBase + (unsigned)s * (BSZ * 2), Bp + (size_t)(t * 16) * N);
    };

    float acc[4][4][4];
#pragma unroll
    for (int mi = 0; mi < 4; mi++)
#pragma unroll
        for (int ni = 0; ni < 4; ni++)
#pragma unroll
            for (int q = 0; q < 4; q++) acc[mi][ni][q] = 0.f;

    issue(0); cp_commit();
    issue(1); cp_commit();
    issue(2); cp_commit();

    int aRowSel = lane & 15;
    int aColSel = (lane >> 4) * 8;
    int bRowSel = lane & 15;

    for (int t = 0; t < nT; t++) {
        cp_wait<2>();
        __syncthreads();
        if (t + 3 < nT) issue(t + 3);
        cp_commit();
        int s = t & (HSTG - 1);
        unsigned aS = aLds + (unsigned)s * (ASZ * 2);
        unsigned bS = bLds + (unsigned)s * (BSZ * 2);

        unsigned afr[4][4];
#pragma unroll
        for (int mi = 0; mi < 4; mi++) {
            int row = wm * 64 + mi * 16 + aRowSel;
            ldsm_x4(afr[mi][0], afr[mi][1], afr[mi][2], afr[mi][3],
                    aS + (unsigned)(row * AST2 + aColSel) * 2);
        }
        unsigned bfr[4][2];
#pragma unroll
        for (int ni = 0; ni < 4; ni++) {
            int n = wn * 32 + ni * 8;
            ldsm_x2t(bfr[ni][0], bfr[ni][1], bS + (unsigned)(bRowSel * BST2 + n) * 2);
        }
#pragma unroll
        for (int ni = 0; ni < 4; ni++)
#pragma unroll
            for (int mi = 0; mi < 4; mi++)
                mma_f16(acc[mi][ni], afr[mi], bfr[ni][0], bfr[ni][1]);
    }

#pragma unroll
    for (int mi = 0; mi < 4; mi++) {
#pragma unroll
        for (int ni = 0; ni < 4; ni++) {
            int row = row0 + wm * 64 + mi * 16 + g;
            int col = col0 + wn * 32 + ni * 8 + 2 * t4;
#pragma unroll
            for (int half_ = 0; half_ < 2; half_++) {
                int r = row + half_ * 8;
                float v0 = acc[mi][ni][half_ * 2 + 0];
                float v1 = acc[mi][ni][half_ * 2 + 1];
                if (bias) { v0 += bias[col]; v1 += bias[col + 1]; }
                if (act) {
                    v0 = 0.5f * v0 * (1.f + erff(v0 * 0.70710678118654752f));
                    v1 = 0.5f * v1 * (1.f + erff(v1 * 0.70710678118654752f));
                }
                if (res) {
                    v0 += res[(size_t)r * N + col];
                    v1 += res[(size_t)r * N + col + 1];
                }
                if (C)  *(float2*)&C[(size_t)r * N + col] = make_float2(v0, v1);
                if (Ch) *(__half2*)&Ch[(size_t)r * N + col] = __floats2half2_rn(v0, v1);
            }
        }
    }
}

// fused QKV: sel 0,1 -> fp32 (q,k for features); sel 2 -> fp16 v
__global__ __launch_bounds__(256, 2)
void gemm_qkv(const __half* __restrict__ A, const __half* __restrict__ Bq,
              const __half* __restrict__ Bk, const __half* __restrict__ Bv,
              float* __restrict__ Cq, float* __restrict__ Ck, __half* __restrict__ CvH)
{
    constexpr int N = cE, K = cE;
    extern __shared__ __half hsm[];
    __half* Asm = hsm;
    __half* Bsm = hsm + (size_t)HSTG * ASZ;

    int tid = threadIdx.x;
    int warp = tid >> 5, lane = tid & 31;
    int wm = warp >> 2, wn = warp & 3;
    int g = lane >> 2, t4 = lane & 3;
    int bx = blockIdx.x;
    int sel = bx >> 2;
    const __half* Bm = sel == 0 ? Bq : (sel == 1 ? Bk : Bv);
    int row0 = blockIdx.y * 128, col0 = (bx & 3) * 128;

    int arow = tid >> 1, ac8 = (tid & 1) * 8;
    int brow = tid >> 4, bc8 = (tid & 15) * 8;

    const __half* Ap = A + (size_t)(row0 + arow) * K + ac8;
    const __half* Bp = Bm + (size_t)brow * N + col0 + bc8;
    unsigned aBase = (unsigned)__cvta_generic_to_shared(Asm) + (unsigned)(arow * AST2 + ac8) * 2;
    unsigned bBase = (unsigned)__cvta_generic_to_shared(Bsm) + (unsigned)(brow * BST2 + bc8) * 2;
    unsigned aLds = (unsigned)__cvta_generic_to_shared(Asm);
    unsigned bLds = (unsigned)__cvta_generic_to_shared(Bsm);

    int nT = K >> 4;

    auto issue = [&](int t) {
        int s = t & (HSTG - 1);
        cp16(aBase + (unsigned)s * (ASZ * 2), Ap + (size_t)t * 16);
        cp16(bBase + (unsigned)s * (BSZ * 2), Bp + (size_t)(t * 16) * N);
    };

    float acc[4][4][4];
#pragma unroll
    for (int mi = 0; mi < 4; mi++)
#pragma unroll
        for (int ni = 0; ni < 4; ni++)
#pragma unroll
            for (int q = 0; q < 4; q++) acc[mi][ni][q] = 0.f;

    issue(0); cp_commit();
    issue(1); cp_commit();
    issue(2); cp_commit();

    int aRowSel = lane & 15;
    int aColSel = (lane >> 4) * 8;
    int bRowSel = lane & 15;

    for (int t = 0; t < nT; t++) {
        cp_wait<2>();
        __syncthreads();
        if (t + 3 < nT) issue(t + 3);
        cp_commit();
        int s = t & (HSTG - 1);
        unsigned aS = aLds + (unsigned)s * (ASZ * 2);
        unsigned bS = bLds + (unsigned)s * (BSZ * 2);

        unsigned afr[4][4];
#pragma unroll
        for (int mi = 0; mi < 4; mi++) {
            int row = wm * 64 + mi * 16 + aRowSel;
            ldsm_x4(afr[mi][0], afr[mi][1], afr[mi][2], afr[mi][3],
                    aS + (unsigned)(row * AST2 + aColSel) * 2);
        }
        unsigned bfr[4][2];
#pragma unroll
        for (int ni = 0; ni < 4; ni++) {
            int n = wn * 32 + ni * 8;
            ldsm_x2t(bfr[ni][0], bfr[ni][1], bS + (unsigned)(bRowSel * BST2 + n) * 2);
        }
#pragma unroll
        for (int ni = 0; ni < 4; ni++)
#pragma unroll
            for (int mi = 0; mi < 4; mi++)
                mma_f16(acc[mi][ni], afr[mi], bfr[ni][0], bfr[ni][1]);
    }

    float* C = sel == 0 ? Cq : Ck;
#pragma unroll
    for (int mi = 0; mi < 4; mi++) {
#pragma unroll
        for (int ni = 0; ni < 4; ni++) {
            int row = row0 + wm * 64 + mi * 16 + g;
            int col = col0 + wn * 32 + ni * 8 + 2 * t4;
#pragma unroll
            for (int half_ = 0; half_ < 2; half_++) {
                int r = row + half_ * 8;
                float v0 = acc[mi][ni][half_ * 2 + 0];
                float v1 = acc[mi][ni][half_ * 2 + 1];
                if (sel == 2)
                    *(__half2*)&CvH[(size_t)r * N + col] = __floats2half2_rn(v0, v1);
                else
                    *(float2*)&C[(size_t)r * N + col] = make_float2(v0, v1);
            }
        }
    }
}

// ---------------- fused FAVOR+ features (q + k) ----------------
constexpr int FPST = 68;
constexpr size_t FEAT2_FLOATS = (size_t)cM * FPST + 2 * 16 * 64 + 32 + 16 * 8 + 8 + 16;
constexpr size_t FEAT2_BYTES = FEAT2_FLOATS * 4;

__global__ void feat_qk_kernel(const float* __restrict__ q, const float* __restrict__ k,
                               const float* __restrict__ proj, __half* __restrict__ qfh,
                               float* __restrict__ kf, float* __restrict__ kdiag,
                               float* __restrict__ gmax)
{
    extern __shared__ float fsm[];
    float* psh    = fsm;
    float* xq     = psh + (size_t)cM * FPST;
    float* xk     = xq + 16 * 64;
    float* ssq    = xk + 16 * 64;
    float* wred   = ssq + 32;
    float* kred   = wred + 128;
    float* rowmax = kred + 8;

    int s0 = blockIdx.x * 16;
    int bh = blockIdx.y;
    int b = bh / cH, h = bh % cH;
    int tid = threadIdx.x;

    for (int i = tid; i < cM * cDH; i += 256)
        psh[(i >> 6) * FPST + (i & 63)] = proj[i];
    for (int i = tid; i < 16 * 64; i += 256) {
        int s = i >> 6, d = i & 63;
        size_t gi = (size_t)(b * cS + s0 + s) * cE + h * cDH + d;
        xq[i] = q[gi];
        xk[i] = k[gi];
    }
    __syncthreads();
    if (tid < 32) {
        const float* xp = (tid < 16) ? xq : xk;
        int s = tid & 15;
        float acc = 0.f;
#pragma unroll
        for (int d = 0; d < 64; d += 4) {
            float4 xv = *(const float4*)&xp[s * 64 + d];
            acc += xv.x * xv.x + xv.y * xv.y + xv.z * xv.z + xv.w * xv.w;
        }
        ssq[tid] = acc;
    }
    const float dn = 0.35355339059327373f;
    int m = tid;
    float xdq[16], xdk[16];
#pragma unroll
    for (int s = 0; s < 16; s++) {
        float dq = 0.f, dk = 0.f;
#pragma unroll
        for (int d = 0; d < 64; d += 4) {
            float4 p  = *(const float4*)&psh[m * FPST + d];
            float4 aq = *(const float4*)&xq[s * 64 + d];
            float4 ck = *(const float4*)&xk[s * 64 + d];
            dq += p.x * aq.x + p.y * aq.y + p.z * aq.z + p.w * aq.w;
            dk += p.x * ck.x + p.y * ck.y + p.z * ck.z + p.w * ck.w;
        }
        xdq[s] = dq * dn;
        xdk[s] = dk * dn;
    }
    int lane = tid & 31, warp = tid >> 5;
#pragma unroll
    for (int s = 0; s < 16; s++) {
        float mx = xdq[s];
#pragma unroll
        for (int sft = 16; sft > 0; sft >>= 1) mx = fmaxf(mx, __shfl_xor_sync(0xffffffff, mx, sft));
        if (lane == 0) wred[s * 8 + warp] = mx;
    }
    float tmax = xdk[0];
#pragma unroll
    for (int s = 1; s < 16; s++) tmax = fmaxf(tmax, xdk[s]);
#pragma unroll
    for (int sft = 16; sft > 0; sft >>= 1) tmax = fmaxf(tmax, __shfl_xor_sync(0xffffffff, tmax, sft));
    if (lane == 0) kred[warp] = tmax;
    __syncthreads();
    if (tid < 16) {
        float mx = wred[tid * 8];
#pragma unroll
        for (int w = 1; w < 8; w++) mx = fmaxf(mx, wred[tid * 8 + w]);
        rowmax[tid] = mx;
        kdiag[(size_t)bh * cS + s0 + tid] = 0.5f * ssq[16 + tid] * dn * dn;
    }
    if (tid == 0) {
        float mx = kred[0];
#pragma unroll
        for (int w = 1; w < 8; w++) mx = fmaxf(mx, kred[w]);
        atomicMaxFloat(gmax, mx);
    }
    __syncthreads();
#pragma unroll
    for (int s = 0; s < 16; s++) {
        float diag = 0.5f * ssq[s] * dn * dn;
        size_t oi = ((size_t)bh * cS + s0 + s) * cM + m;
        qfh[oi] = __float2half(0.0625f * (expf(xdq[s] - diag - rowmax[s]) + 1e-4f));
        kf[oi] = xdk[s];
    }
}

__global__ void feat_k2_kernel(const float* __restrict__ kf, __half* __restrict__ kfh,
                               const float* __restrict__ kdiag, const float* __restrict__ gmax)
{
    float gm = *gmax;
    size_t total = (size_t)cBH * cS * cM;
    for (size_t i = (size_t)blockIdx.x * blockDim.x + threadIdx.x; i < total;
         i += (size_t)gridDim.x * blockDim.x) {
        kfh[i] = __float2half(0.0625f * (expf(kf[i] - kdiag[i >> 8] - gm) + 1e-4f));
    }
}

// ---------------- attention phase A: per-chunk state sums (fp16 in, fp32 out) ----------------
__global__ void attn_chunk_sums(const __half* __restrict__ kfh, const __half* __restrict__ vH,
                                float* __restrict__ kvsum, float* __restrict__ zc)
{
    __shared__ float vsh[cCHUNK * cDH];
    int ch = blockIdx.x, bh = blockIdx.y;
    int b = bh / cH, h = bh % cH;
    int tid = threadIdx.x;
    int c0 = ch * cCHUNK;
    const __half* v_b = vH + (size_t)b * cS * cE + h * cDH;
    for (int i = tid; i < cCHUNK * cDH; i += 256) {
        int c = i >> 6, d = i & 63;
        vsh[i] = __half2float(v_b[(size_t)(c0 + c) * cE + d]);
    }
    __syncthreads();
    int m = tid;
    float acc[cDH];
#pragma unroll
    for (int d = 0; d < cDH; d++) acc[d] = 0.f;
    float zacc = 0.f;
    const __half* kf_b = kfh + ((size_t)bh * cS + c0) * cM + m;
    for (int i = 0; i < cCHUNK; i++) {
        float kv = __half2float(kf_b[(size_t)i * cM]);
        zacc += kv;
        const float4* vr = (const float4*)&vsh[i * cDH];
#pragma unroll
        for (int j = 0; j < 16; j++) {
            float4 vv = vr[j];
            acc[j * 4 + 0] += kv * vv.x;
            acc[j * 4 + 1] += kv * vv.y;
            acc[j * 4 + 2] += kv * vv.z;
            acc[j * 4 + 3] += kv * vv.w;
        }
    }
    float* outp = kvsum + (((size_t)bh * cNC + ch) * cM + m) * cDH;
#pragma unroll
    for (int d = 0; d < cDH; d += 4)
        *(float4*)&outp[d] = make_float4(acc[d], acc[d + 1], acc[d + 2], acc[d + 3]);
    zc[((size_t)bh * cNC + ch) * cM + m] = zacc;
}

// ---------------- attention phase B: exclusive prefix -> fp16 [Sp|z] (stride 72) ----------------
__global__ void attn_prefix(const float* __restrict__ kvsum, const float* __restrict__ zc,
                            __half* __restrict__ sphg)
{
    int bh = blockIdx.x, ds = blockIdx.y;
    int m = threadIdx.x;
    int d0 = ds * 16;
    float carry[16];
#pragma unroll
    for (int j = 0; j < 16; j++) carry[j] = 0.f;
    float zcarry = 0.f;
    for (int c = 0; c < cNC; c++) {
        const float* p = kvsum + (((size_t)bh * cNC + c) * cM + m) * cDH + d0;
        __half* sp = sphg + (((size_t)bh * cNC + c) * cM + m) * 72 + d0;
#pragma unroll
        for (int j = 0; j < 16; j++) {
            sp[j] = __float2half(carry[j]);
            carry[j] += p[j];
        }
        if (ds == 0) {
            __half* spz = sphg + (((size_t)bh * cNC + c) * cM + m) * 72;
            spz[64] = __float2half(zcarry);
#pragma unroll
            for (int j = 65; j < 72; j++) spz[j] = __float2half(0.f);
            zcarry += zc[((size_t)bh * cNC + c) * cM + m];
        }
    }
}

// ---------------- attention phase C: fully-MMA per-chunk output ----------------
constexpr int QST = 264;     // qh/kh stride (halves): 132 words % 32 = 4 -> conflict-free ldsm
constexpr int ASH_ST = 136;  // Ash stride
constexpr int VST = 88;      // vh/sph stride
constexpr size_t ATT2_HALVES = (size_t)128 * QST * 2 + 128 * VST + 256 * VST;
constexpr size_t ATT2_BYTES = ATT2_HALVES * 2;   // 202752

__global__ void attn_out(const __half* __restrict__ qfh, const __half* __restrict__ kfh,
                         const __half* __restrict__ vH, const __half* __restrict__ sphg,
                         __half* __restrict__ oH)
{
    extern __shared__ __half hsm2[];
    __half* qh  = hsm2;                       // [128][264]  qf chunk [c][m]
    __half* kh  = qh + 128 * QST;             // [128][264]  kf chunk [t][m]; later Ash [c][t] str 136
    __half* vh  = kh + 128 * QST;             // [128][88]   [t][d], col64 = 1
    __half* sph = vh + 128 * VST;             // [256][88]   [m][d], col64 = z

    int ch = blockIdx.x, bh = blockIdx.y;
    int b = bh / cH, h = bh % cH;
    int tid = threadIdx.x, warp = tid >> 5, lane = tid & 31;
    int c0 = ch * cCHUNK;

    const __half* qg = qfh + ((size_t)bh * cS + c0) * cM;
    const __half* kg = kfh + ((size_t)bh * cS + c0) * cM;
    for (int i = tid; i < 128 * 32; i += 256) {
        int r = i >> 5, c = (i & 31) * 8;
        *(uint4*)&qh[r * QST + c] = *(const uint4*)&qg[(size_t)r * cM + c];
        *(uint4*)&kh[r * QST + c] = *(const uint4*)&kg[(size_t)r * cM + c];
    }
    const __half* vg = vH + (size_t)(b * cS + c0) * cE + h * cDH;
    for (int i = tid; i < 128 * 8; i += 256) {
        int r = i >> 3, c = (i & 7) * 8;
        *(uint4*)&vh[r * VST + c] = *(const uint4*)&vg[(size_t)r * cE + c];
    }
    for (int i = tid; i < 128 * 24; i += 256) {
        int r = i / 24, c = i % 24;
        vh[r * VST + 64 + c] = (c == 0) ? __float2half(1.f) : __float2half(0.f);
    }
    const __half* sg = sphg + ((size_t)bh * cNC + ch) * cM * 72;
    for (int i = tid; i < 256 * 9; i += 256) {
        int r = i / 9, c = (i % 9) * 8;
        *(uint4*)&sph[r * VST + c] = *(const uint4*)&sg[(size_t)r * 72 + c];
    }
    for (int i = tid; i < 256 * 16; i += 256) {
        int r = i >> 4, c = i & 15;
        sph[r * VST + 72 + c] = __float2half(0.f);
    }
    __syncthreads();

    unsigned qb = (unsigned)__cvta_generic_to_shared(qh);
    unsigned kb = (unsigned)__cvta_generic_to_shared(kh);
    unsigned vb = (unsigned)__cvta_generic_to_shared(vh);
    unsigned sb = (unsigned)__cvta_generic_to_shared(sph);

    int l16 = lane & 15, lhi = lane >> 4;
    int lq = lane & 7, grp = lane >> 3;
    int g = lane >> 2, t4 = lane & 3;

    // ---- phase 1: A = qf @ kf^T (128x128, k=256), warps (2,4) 64x32 tiles ----
    {
        int wm = warp >> 2, wn = warp & 3;
        float accA[4][4][4];
#pragma unroll
        for (int mi = 0; mi < 4; mi++)
#pragma unroll
            for (int ni = 0; ni < 4; ni++)
#pragma unroll
                for (int q = 0; q < 4; q++) accA[mi][ni][q] = 0.f;

        for (int ks = 0; ks < 16; ks++) {
            int k0 = ks * 16;
            unsigned af[4][4];
#pragma unroll
            for (int mi = 0; mi < 4; mi++)
                ldsm_x4(af[mi][0], af[mi][1], af[mi][2], af[mi][3],
                        qb + (unsigned)((wm * 64 + mi * 16 + l16) * QST + k0 + 8 * lhi) * 2);
            unsigned bfA[2][4];
#pragma unroll
            for (int g16 = 0; g16 < 2; g16++) {
                int n0 = wn * 32 + g16 * 16;
                int nrow = n0 + lq + ((grp & 2) ? 8 : 0);
                int kcol = k0 + ((grp & 1) ? 8 : 0);
                ldsm_x4(bfA[g16][0], bfA[g16][1], bfA[g16][2], bfA[g16][3],
                        kb + (unsigned)(nrow * QST + kcol) * 2);
            }
#pragma unroll
            for (int ni = 0; ni < 4; ni++) {
                unsigned b0 = bfA[ni >> 1][(ni & 1) * 2];
                unsigned b1 = bfA[ni >> 1][(ni & 1) * 2 + 1];
#pragma unroll
                for (int mi = 0; mi < 4; mi++)
                    mma_f16(accA[mi][ni], af[mi], b0, b1);
            }
        }
        __syncthreads();   // all reads of kh done
        // masked store A -> Ash (kh region, stride 136)
#pragma unroll
        for (int mi = 0; mi < 4; mi++) {
#pragma unroll
            for (int ni = 0; ni < 4; ni++) {
                int row = wm * 64 + mi * 16 + g;
                int col = wn * 32 + ni * 8 + 2 * t4;
                float a0 = (col <= row) ? accA[mi][ni][0] : 0.f;
                float a1 = (col + 1 <= row) ? accA[mi][ni][1] : 0.f;
                *(__half2*)&kh[row * ASH_ST + col] = __floats2half2_rn(a0, a1);
                int row2 = row + 8;
                float a2 = (col <= row2) ? accA[mi][ni][2] : 0.f;
                float a3 = (col + 1 <= row2) ? accA[mi][ni][3] : 0.f;
                *(__half2*)&kh[row2 * ASH_ST + col] = __floats2half2_rn(a2, a3);
            }
        }
        __syncthreads();
    }

    // ---- phase 2: [num|den] = qf @ [Sp|z] + Ash @ [v|1]  (128x72), warps: 16 rows each ----
    float accN[9][4];
#pragma unroll
    for (int j = 0; j < 9; j++)
#pragma unroll
        for (int q = 0; q < 4; q++) accN[j][q] = 0.f;

    int m0 = warp * 16;
    // num1: k = 256 over qh / sph
    for (int ks = 0; ks < 16; ks++) {
        int k0 = ks * 16;
        unsigned af4[4];
        ldsm_x4(af4[0], af4[1], af4[2], af4[3],
                qb + (unsigned)((m0 + l16) * QST + k0 + 8 * lhi) * 2);
        unsigned bf[5][4];
        int krow = k0 + lq + ((grp & 1) ? 8 : 0);
#pragma unroll
        for (int nf = 0; nf < 5; nf++) {
            int ncol = nf * 16 + ((grp & 2) ? 8 : 0);
            ldsm_x4t(bf[nf][0], bf[nf][1], bf[nf][2], bf[nf][3],
                     sb + (unsigned)(krow * VST + ncol) * 2);
        }
#pragma unroll
        for (int j = 0; j < 9; j++) {
            int nf = j >> 1, p = j & 1;
            mma_f16(accN[j], af4, bf[nf][p * 2], bf[nf][p * 2 + 1]);
        }
    }
    // num2: k = 128 over Ash / vh
    for (int ks = 0; ks < 8; ks++) {
        int k0 = ks * 16;
        unsigned af4[4];
        ldsm_x4(af4[0], af4[1], af4[2], af4[3],
                kb + (unsigned)((m0 + l16) * ASH_ST + k0 + 8 * lhi) * 2);
        unsigned bf[5][4];
        int krow = k0 + lq + ((grp & 1) ? 8 : 0);
#pragma unroll
        for (int nf = 0; nf < 5; nf++) {
            int ncol = nf * 16 + ((grp & 2) ? 8 : 0);
            ldsm_x4t(bf[nf][0], bf[nf][1], bf[nf][2], bf[nf][3],
                     vb + (unsigned)(krow * VST + ncol) * 2);
        }
#pragma unroll
        for (int j = 0; j < 9; j++) {
            int nf = j >> 1, p = j & 1;
            mma_f16(accN[j], af4, bf[nf][p * 2], bf[nf][p * 2 + 1]);
        }
    }

    // epilogue: den = col 64 (frag 8, t4==0 lanes); broadcast within 4-lane groups
    float denlo = __shfl_sync(0xffffffff, accN[8][0], lane & ~3);
    float denhi = __shfl_sync(0xffffffff, accN[8][2], lane & ~3);
    float invlo = 1.f / (denlo + 1e-6f);
    float invhi = 1.f / (denhi + 1e-6f);
    int rowlo = m0 + g, rowhi = rowlo + 8;
    __half* olo = oH + (size_t)(b * cS + c0 + rowlo) * cE + h * cDH;
    __half* ohi = oH + (size_t)(b * cS + c0 + rowhi) * cE + h * cDH;
#pragma unroll
    for (int nf = 0; nf < 8; nf++) {
        int col = nf * 8 + 2 * t4;
        *(__half2*)&olo[col] = __floats2half2_rn(accN[nf][0] * invlo, accN[nf][1] * invlo);
        *(__half2*)&ohi[col] = __floats2half2_rn(accN[nf][2] * invhi, accN[nf][3] * invhi);
    }
}

// ---------------- host orchestration ----------------
extern "C" void kernel_launch(void* const* d_in, const int* in_sizes, int n_in,
                              void* d_out, int out_size)
{
    const int*   src  = (const int*)d_in[0];
    const float* emb  = (const float*)d_in[2];
    const float* lng  = (const float*)d_in[3];
    const float* lnb  = (const float*)d_in[4];
    const float* Wq   = (const float*)d_in[5];
    const float* Wk   = (const float*)d_in[6];
    const float* Wv   = (const float*)d_in[7];
    const float* Wo   = (const float*)d_in[8];
    const float* ln1g = (const float*)d_in[9];
    const float* ln1b = (const float*)d_in[10];
    const float* W1   = (const float*)d_in[11];
    const float* b1   = (const float*)d_in[12];
    const float* W2   = (const float*)d_in[13];
    const float* b2   = (const float*)d_in[14];
    const float* ln2g = (const float*)d_in[15];
    const float* ln2b = (const float*)d_in[16];
    const float* proj = (const float*)d_in[17];
    const float* fcw  = (const float*)d_in[18];
    const float* fcb  = (const float*)d_in[19];
    float* out = (float*)d_out;

    float* sc = nullptr;
    cudaGetSymbolAddress((void**)&sc, g_scratch);
    __half* sh = nullptr;
    cudaGetSymbolAddress((void**)&sh, g_scratch_h);

    float* x    = sc + OFF_X;
    float* q    = sc + OFF_Q;
    float* k    = sc + OFF_K;
    float* kf   = sc + OFF_KF;
    float* kd   = sc + OFF_KD;
    float* kvs  = sc + OFF_KV;
    float* zcb  = sc + OFF_ZC;
    float* gmax = sc + OFF_GMAX;

    __half* hH   = sh + HOFF_H;
    __half* oH   = sh + HOFF_O;
    __half* ffnH = sh + HOFF_FFN;
    __half* xH   = sh + HOFF_XH;
    __half* vH   = sh + HOFF_VH;
    __half* qfh  = sh + HOFF_QFH;
    __half* kfh  = sh + HOFF_KFH;
    __half* sphg = sh + HOFF_SPH;
    __half* WqH  = sh + HOFF_WQ;
    __half* WkH  = sh + HOFF_WK;
    __half* WvH  = sh + HOFF_WV;
    __half* WoH  = sh + HOFF_WO;
    __half* W1H  = sh + HOFF_W1;
    __half* W2H  = sh + HOFF_W2;
    __half* fcwH = sh + HOFF_FCW;

    cudaFuncSetAttribute(gemm_f16, cudaFuncAttributeMaxDynamicSharedMemorySize, (int)GEMM_SMEM_BYTES);
    cudaFuncSetAttribute(gemm_qkv, cudaFuncAttributeMaxDynamicSharedMemorySize, (int)GEMM_SMEM_BYTES);
    cudaFuncSetAttribute(attn_out, cudaFuncAttributeMaxDynamicSharedMemorySize, (int)ATT2_BYTES);
    cudaFuncSetAttribute(feat_qk_kernel, cudaFuncAttributeMaxDynamicSharedMemorySize, (int)FEAT2_BYTES);

    int nWsm = cL * cE * cE / 4;
    int nWff = cL * cE * 4 * cE / 4;
    int nFcw = cE * cV / 4;
    f2h_kernel<<<512, 256>>>(Wq, WqH, nWsm);
    f2h_kernel<<<512, 256>>>(Wk, WkH, nWsm);
    f2h_kernel<<<512, 256>>>(Wv, WvH, nWsm);
    f2h_kernel<<<512, 256>>>(Wo, WoH, nWsm);
    f2h_kernel<<<1024, 256>>>(W1, W1H, nWff);
    f2h_kernel<<<1024, 256>>>(W2, W2H, nWff);
    f2h_kernel<<<2048, 256>>>(fcw, fcwH, nFcw);

    embed_ln_kernel<<<cBS, 256>>>(src, emb, lng, lnb, x);

    dim3 g512(cE / 128, cBS / 128);
    dim3 gF1(4 * cE / 128, cBS / 128);
    dim3 gQKV(12, cBS / 128);
    dim3 gFeat(cS / 16, cBH);
    dim3 gChunk(cNC, cBH);
    dim3 gPfx(cBH, 4);

    for (int l = 0; l < cL; l++) {
        ln_kernel_h<<<cBS, 256>>>(x, ln1g + (size_t)l * cE, ln1b + (size_t)l * cE, hH, gmax);
        gemm_qkv<<<gQKV, 256, GEMM_SMEM_BYTES>>>(hH, WqH + (size_t)l * cE * cE,
                                                 WkH + (size_t)l * cE * cE,
                                                 WvH + (size_t)l * cE * cE, q, k, vH);

        const float* pl = proj + (size_t)l * cM * cDH;
        feat_qk_kernel<<<gFeat, 256, FEAT2_BYTES>>>(q, k, pl, qfh, kf, kd, gmax);
        feat_k2_kernel<<<4096, 256>>>(kf, kfh, kd, gmax);

        attn_chunk_sums<<<gChunk, 256>>>(kfh, vH, kvs, zcb);
        attn_prefix<<<gPfx, 256>>>(kvs, zcb, sphg);
        attn_out<<<gChunk, 256, ATT2_BYTES>>>(qfh, kfh, vH, sphg, oH);

        gemm_f16<<<g512, 256, GEMM_SMEM_BYTES>>>(oH, WoH + (size_t)l * cE * cE,
                                                 nullptr, x, x, nullptr, cE, cE, 0);

        ln_kernel_h<<<cBS, 256>>>(x, ln2g + (size_t)l * cE, ln2b + (size_t)l * cE, hH, nullptr);
        gemm_f16<<<gF1, 256, GEMM_SMEM_BYTES>>>(hH, W1H + (size_t)l * cE * 4 * cE,
                                                b1 + (size_t)l * 4 * cE, nullptr,
                                                nullptr, ffnH, 4 * cE, cE, 1);
        gemm_f16<<<g512, 256, GEMM_SMEM_BYTES>>>(ffnH, W2H + (size_t)l * cE * 4 * cE,
                                                 b2 + (size_t)l * cE, x, x, xH, cE, 4 * cE, 0);
    }

    gemm_f16<<<dim3(cV / 128, cBS / 128), 256, GEMM_SMEM_BYTES>>>(
        xH, fcwH, fcb, nullptr, out, nullptr, cV, cE, 0);
}